// round 2
// baseline (speedup 1.0000x reference)
#include <cuda_runtime.h>
#include <cuda_bf16.h>
#include <math.h>

// Problem constants
#define BATCH   64
#define NTOK    236
#define CDIM    768
#define HEADS   8
#define HDIM    96
#define C3      2304
#define S1C     196
#define S2C     216
#define BIASV   100.0f

#define MROWS   (BATCH * NTOK)   // 15104

// Scratch (device globals; no allocation allowed)
__device__ float g_qkv[(size_t)MROWS * C3];   // [15104, 2304]
__device__ float g_att[(size_t)MROWS * CDIM]; // [15104, 768]

// ---------------------------------------------------------------------------
// Tiled SGEMM: C[m,n] = sum_k A[m,k] * W[n,k] (+ bias[n])
// A: [M,K] row-major, W: [N,K] row-major. M%128==0, N%128==0, K%16==0.
// ---------------------------------------------------------------------------
#define BM 128
#define BN 128
#define BK 16

__global__ __launch_bounds__(256) void sgemm_nt_kernel(
    const float* __restrict__ A, const float* __restrict__ W,
    const float* __restrict__ bias, float* __restrict__ C,
    int M, int Nc, int K)
{
    __shared__ float As[BK][BM + 4];
    __shared__ float Ws[BK][BN + 4];

    const int tid = threadIdx.x;
    const int tx = tid & 15;         // 0..15 -> n
    const int ty = tid >> 4;         // 0..15 -> m
    const int m0 = blockIdx.y * BM;
    const int n0 = blockIdx.x * BN;

    float acc[8][8];
#pragma unroll
    for (int i = 0; i < 8; i++)
#pragma unroll
        for (int j = 0; j < 8; j++) acc[i][j] = 0.f;

    for (int k0 = 0; k0 < K; k0 += BK) {
        // Load tiles: 512 float4 each, 2 per thread
#pragma unroll
        for (int v = tid; v < 512; v += 256) {
            int r  = v >> 2;
            int kk = (v & 3) << 2;
            float4 a = *(const float4*)(A + (size_t)(m0 + r) * K + k0 + kk);
            As[kk + 0][r] = a.x; As[kk + 1][r] = a.y;
            As[kk + 2][r] = a.z; As[kk + 3][r] = a.w;
            float4 wv = *(const float4*)(W + (size_t)(n0 + r) * K + k0 + kk);
            Ws[kk + 0][r] = wv.x; Ws[kk + 1][r] = wv.y;
            Ws[kk + 2][r] = wv.z; Ws[kk + 3][r] = wv.w;
        }
        __syncthreads();

#pragma unroll
        for (int kk = 0; kk < BK; kk++) {
            float afr[8], bfr[8];
            *(float4*)(afr)     = *(const float4*)&As[kk][ty * 8];
            *(float4*)(afr + 4) = *(const float4*)&As[kk][ty * 8 + 4];
            *(float4*)(bfr)     = *(const float4*)&Ws[kk][tx * 8];
            *(float4*)(bfr + 4) = *(const float4*)&Ws[kk][tx * 8 + 4];
#pragma unroll
            for (int i = 0; i < 8; i++)
#pragma unroll
                for (int j = 0; j < 8; j++)
                    acc[i][j] = fmaf(afr[i], bfr[j], acc[i][j]);
        }
        __syncthreads();
    }

    // Epilogue
#pragma unroll
    for (int i = 0; i < 8; i++) {
        int row = m0 + ty * 8 + i;
        float* cp = C + (size_t)row * Nc + n0 + tx * 8;
        if (bias) {
            const float* bp = bias + n0 + tx * 8;
#pragma unroll
            for (int j = 0; j < 8; j++) acc[i][j] += bp[j];
        }
        float4 v0 = make_float4(acc[i][0], acc[i][1], acc[i][2], acc[i][3]);
        float4 v1 = make_float4(acc[i][4], acc[i][5], acc[i][6], acc[i][7]);
        *(float4*)(cp)     = v0;
        *(float4*)(cp + 4) = v1;
    }
}

// ---------------------------------------------------------------------------
// Fused attention per (b,h): scores = q k^T * scale, block edits, softmax, @v
// One CTA per (b,h). K/V resident in shared memory (zero-padded to 256 rows).
// Warps process 4 query rows at a time with 8-column register blocking.
// ---------------------------------------------------------------------------
#define KSTR 97
#define SM_KS   (256 * KSTR)          // 24832
#define SM_VS   (256 * HDIM)          // 24576
#define SM_QS   (8 * 4 * HDIM)        // 3072
#define SM_SR   (8 * 256)             // 2048
#define ATT_SMEM_FLOATS (SM_KS + SM_VS + SM_QS + SM_SR)
#define ATT_SMEM_BYTES  (ATT_SMEM_FLOATS * 4)

__global__ __launch_bounds__(256) void attn_kernel(
    const float* __restrict__ qkv, float* __restrict__ out)
{
    extern __shared__ float sm[];
    float* ks   = sm;                       // [256][97]
    float* vs   = ks + SM_KS;               // [256][96]
    float* qs   = vs + SM_VS;               // [8][4][96]
    float* srow = qs + SM_QS;               // [8][256]

    const int bh = blockIdx.x;
    const int b = bh >> 3, h = bh & 7;
    const int tid = threadIdx.x;
    const int w = tid >> 5, lane = tid & 31;
    const float scale = 0.1020620726159658f;   // 96^-0.5

    const size_t base = (size_t)b * NTOK * C3;

    // Stage K and V into smem (rows 236..255 zero-filled)
    for (int idx = tid; idx < 256 * HDIM; idx += 256) {
        int m = idx / HDIM;
        int d = idx - m * HDIM;
        float kv = 0.f, vv = 0.f;
        if (m < NTOK) {
            const float* row = qkv + base + (size_t)m * C3 + h * HDIM + d;
            kv = row[CDIM];      // k block
            vv = row[2 * CDIM];  // v block
        }
        ks[m * KSTR + d] = kv;
        vs[m * HDIM + d] = vv;
    }
    __syncthreads();

    float* myq = qs + w * (4 * HDIM);
    float* mys = srow + w * 256;

    // 236 rows = 59 groups of 4
    for (int g = w; g < 59; g += 8) {
        const int n0 = g * 4;

        // Stage 4 q rows
        for (int i = lane; i < 4 * HDIM; i += 32) {
            int r = i / HDIM;
            int d = i - r * HDIM;
            myq[i] = qkv[base + (size_t)(n0 + r) * C3 + h * HDIM + d];
        }
        __syncwarp();

        float acc[4][8];
#pragma unroll
        for (int r = 0; r < 4; r++)
#pragma unroll
            for (int j = 0; j < 8; j++) acc[r][j] = 0.f;

#pragma unroll 2
        for (int d = 0; d < HDIM; d++) {
            float q0 = myq[d];
            float q1 = myq[HDIM + d];
            float q2 = myq[2 * HDIM + d];
            float q3 = myq[3 * HDIM + d];
#pragma unroll
            for (int j = 0; j < 8; j++) {
                float kv = ks[(j * 32 + lane) * KSTR + d];
                acc[0][j] = fmaf(q0, kv, acc[0][j]);
                acc[1][j] = fmaf(q1, kv, acc[1][j]);
                acc[2][j] = fmaf(q2, kv, acc[2][j]);
                acc[3][j] = fmaf(q3, kv, acc[3][j]);
            }
        }

#pragma unroll 1
        for (int r = 0; r < 4; r++) {
            const int n = n0 + r;
            // scaled scores into smem row
#pragma unroll
            for (int j = 0; j < 8; j++)
                mys[j * 32 + lane] = acc[r][j] * scale;
            __syncwarp();

            // block-wise edits (copy uses pre-bias values)
            if (n < S1C) {
                if (lane < (S2C - S1C)) {
                    float cp = mys[S1C + lane];
                    mys[S2C + lane] = cp;            // copy cols [S1,S2) -> [S2,236)
                    mys[S1C + lane] = cp - BIASV;    // then bias cols [S1,S2)
                }
            } else if (n < S2C) {
                if (lane < (NTOK - S2C)) mys[S2C + lane] -= BIASV;
            } else {
                if (lane < (S2C - S1C)) mys[S1C + lane] -= BIASV;
            }
            __syncwarp();

            // softmax over 236 valid columns
            float vals[8];
            float vmax = -1e30f;
#pragma unroll
            for (int j = 0; j < 8; j++) {
                int m = j * 32 + lane;
                vals[j] = (m < NTOK) ? mys[m] : -1e30f;
                vmax = fmaxf(vmax, vals[j]);
            }
#pragma unroll
            for (int o = 16; o > 0; o >>= 1)
                vmax = fmaxf(vmax, __shfl_xor_sync(0xFFFFFFFFu, vmax, o));
            float ssum = 0.f;
#pragma unroll
            for (int j = 0; j < 8; j++) {
                float e = expf(vals[j] - vmax);   // exp(-1e30) == 0 for pad cols
                ssum += e;
                mys[j * 32 + lane] = e;
            }
#pragma unroll
            for (int o = 16; o > 0; o >>= 1)
                ssum += __shfl_xor_sync(0xFFFFFFFFu, ssum, o);
            const float inv = 1.f / ssum;
            __syncwarp();

            // out_row = p @ V  (lane covers d = lane, lane+32, lane+64)
            float o0 = 0.f, o1 = 0.f, o2 = 0.f;
#pragma unroll 4
            for (int m = 0; m < NTOK; m++) {
                float p = mys[m];
                o0 = fmaf(p, vs[m * HDIM + lane], o0);
                o1 = fmaf(p, vs[m * HDIM + lane + 32], o1);
                o2 = fmaf(p, vs[m * HDIM + lane + 64], o2);
            }
            size_t ob = (size_t)(b * NTOK + n) * CDIM + h * HDIM + lane;
            out[ob]      = o0 * inv;
            out[ob + 32] = o1 * inv;
            out[ob + 64] = o2 * inv;
            __syncwarp();   // protect mys before next row overwrites it
        }
    }
}

// ---------------------------------------------------------------------------
// Launch
// ---------------------------------------------------------------------------
extern "C" void kernel_launch(void* const* d_in, const int* in_sizes, int n_in,
                              void* d_out, int out_size)
{
    const float* x      = (const float*)d_in[0];   // [64,236,768]
    const float* qkv_w  = (const float*)d_in[1];   // [2304,768]
    const float* proj_w = (const float*)d_in[2];   // [768,768]
    const float* proj_b = (const float*)d_in[3];   // [768]
    float* out = (float*)d_out;                    // [64,236,768]

    float* qkv_buf = nullptr;
    float* att_buf = nullptr;
    cudaGetSymbolAddress((void**)&qkv_buf, g_qkv);
    cudaGetSymbolAddress((void**)&att_buf, g_att);

    // 1) QKV projection: [15104,768] @ [2304,768]^T -> [15104,2304]
    {
        dim3 grid(C3 / BN, MROWS / BM);   // (18, 118)
        sgemm_nt_kernel<<<grid, 256>>>(x, qkv_w, nullptr, qkv_buf,
                                       MROWS, C3, CDIM);
    }

    // 2) Fused attention: 512 CTAs, one per (b,h)
    {
        cudaFuncSetAttribute(attn_kernel,
                             cudaFuncAttributeMaxDynamicSharedMemorySize,
                             ATT_SMEM_BYTES);
        attn_kernel<<<BATCH * HEADS, 256, ATT_SMEM_BYTES>>>(qkv_buf, att_buf);
    }

    // 3) Output projection: [15104,768] @ [768,768]^T + b -> [15104,768]
    {
        dim3 grid(CDIM / BN, MROWS / BM); // (6, 118)
        sgemm_nt_kernel<<<grid, 256>>>(att_buf, proj_w, proj_b, out,
                                       MROWS, CDIM, CDIM);
    }
}

// round 3
// speedup vs baseline: 1.7509x; 1.7509x over previous
#include <cuda_runtime.h>
#include <cuda_bf16.h>
#include <math.h>

// Problem constants
#define BATCH   64
#define NTOK    236
#define CDIM    768
#define HEADS   8
#define HDIM    96
#define C3      2304
#define S1C     196
#define S2C     216
#define BIASV   100.0f
#define MROWS   (BATCH * NTOK)   // 15104

// Scratch (device globals; no allocation allowed)
__device__ float g_qkv[(size_t)MROWS * C3];   // [15104, 2304]
__device__ float g_att[(size_t)MROWS * CDIM]; // [15104, 768]

// ===========================================================================
// Split-bf16 tensor-core GEMM:  C[m,n] = sum_k A[m,k] * W[n,k]  (+ bias[n])
// Each fp32 operand split into hi/lo bf16; acc += Ah*Bh + Ah*Bl + Al*Bh.
// Tile 128x128x32, 256 threads (8 warps, 2m x 4n), warp tile 64x32.
// ===========================================================================
#define GBM 128
#define GBN 128
#define GBK 32
#define SSTR 40                       // bf16 row stride (conflict-free ldmatrix)
#define TILE_HALF (GBM * SSTR)        // 5120 bf16 per (buf,split)
#define GEMM_SMEM_BYTES (8 * TILE_HALF * 2)   // A:4 tiles + B:4 tiles = 81920 B

__device__ __forceinline__ void ldsm4(unsigned* r, const __nv_bfloat16* p) {
    unsigned addr = (unsigned)__cvta_generic_to_shared(p);
    asm volatile("ldmatrix.sync.aligned.m8n8.x4.shared.b16 {%0,%1,%2,%3}, [%4];\n"
        : "=r"(r[0]), "=r"(r[1]), "=r"(r[2]), "=r"(r[3]) : "r"(addr));
}

__device__ __forceinline__ void mma_bf16(float* c, const unsigned* a,
                                         unsigned b0, unsigned b1) {
    asm volatile(
        "mma.sync.aligned.m16n8k16.row.col.f32.bf16.bf16.f32 "
        "{%0,%1,%2,%3}, {%4,%5,%6,%7}, {%8,%9}, {%0,%1,%2,%3};\n"
        : "+f"(c[0]), "+f"(c[1]), "+f"(c[2]), "+f"(c[3])
        : "r"(a[0]), "r"(a[1]), "r"(a[2]), "r"(a[3]), "r"(b0), "r"(b1));
}

__device__ __forceinline__ void split_store(__nv_bfloat16* hi, __nv_bfloat16* lo,
                                            const float* f) {
#pragma unroll
    for (int p = 0; p < 2; p++) {
        float f0 = f[p * 2], f1 = f[p * 2 + 1];
        __nv_bfloat16 h0 = __float2bfloat16(f0);
        __nv_bfloat16 h1 = __float2bfloat16(f1);
        __nv_bfloat16 l0 = __float2bfloat16(f0 - __bfloat162float(h0));
        __nv_bfloat16 l1 = __float2bfloat16(f1 - __bfloat162float(h1));
        *(__nv_bfloat162*)(hi + p * 2) = __halves2bfloat162(h0, h1);
        *(__nv_bfloat162*)(lo + p * 2) = __halves2bfloat162(l0, l1);
    }
}

__global__ __launch_bounds__(256, 1) void gemm_bf16x3(
    const float* __restrict__ A, const float* __restrict__ W,
    const float* __restrict__ bias, float* __restrict__ C,
    int M, int Nc, int K)
{
    extern __shared__ __nv_bfloat16 sm[];
    __nv_bfloat16* sA = sm;                     // [buf][hi/lo][TILE_HALF]
    __nv_bfloat16* sB = sm + 4 * TILE_HALF;

    const int tid = threadIdx.x;
    const int lane = tid & 31, wid = tid >> 5;
    const int wm = wid & 1, wn = wid >> 1;      // 2 x 4 warp grid
    const int m0 = blockIdx.y * GBM, n0 = blockIdx.x * GBN;

    // global staging: 2 threads per row, 16 floats each
    const int lrow = tid >> 1;
    const int lk0 = (tid & 1) * 16;
    const float* Ap = A + (size_t)(m0 + lrow) * K + lk0;
    const float* Wp = W + (size_t)(n0 + lrow) * K + lk0;

    // ldmatrix lane addressing
    const int aRow = lane & 15;
    const int aKh = (lane >> 4) * 8;
    const int bNoff = ((lane >> 4) & 1) * 8 + (lane & 7);
    const int bKoff = ((lane >> 3) & 1) * 8;

    float acc[4][4][4];
#pragma unroll
    for (int i = 0; i < 4; i++)
#pragma unroll
        for (int j = 0; j < 4; j++)
#pragma unroll
            for (int q = 0; q < 4; q++) acc[i][j][q] = 0.f;

    float ra[16], rb[16];

#define LOADREGS(K0) do {                                                   \
    _Pragma("unroll")                                                       \
    for (int q = 0; q < 4; q++) {                                           \
        *(float4*)(ra + q * 4) = *(const float4*)(Ap + (K0) + q * 4);       \
        *(float4*)(rb + q * 4) = *(const float4*)(Wp + (K0) + q * 4);       \
    } } while (0)

#define STORESM(BUF) do {                                                   \
    __nv_bfloat16* aH = sA + ((BUF) * 2) * TILE_HALF + lrow * SSTR + lk0;   \
    __nv_bfloat16* bH = sB + ((BUF) * 2) * TILE_HALF + lrow * SSTR + lk0;   \
    _Pragma("unroll")                                                       \
    for (int q = 0; q < 4; q++) {                                           \
        split_store(aH + q * 4, aH + q * 4 + TILE_HALF, ra + q * 4);        \
        split_store(bH + q * 4, bH + q * 4 + TILE_HALF, rb + q * 4);        \
    } } while (0)

    LOADREGS(0);
    STORESM(0);
    __syncthreads();

    const int nk = K / GBK;
    for (int kt = 0; kt < nk; kt++) {
        const int buf = kt & 1;
        if (kt + 1 < nk) LOADREGS((kt + 1) * GBK);

        const __nv_bfloat16* baseAH = sA + (buf * 2) * TILE_HALF;
        const __nv_bfloat16* baseBH = sB + (buf * 2) * TILE_HALF;
#pragma unroll
        for (int ks = 0; ks < 2; ks++) {
            unsigned aH[4][4], aL[4][4], bHr[2][4], bLr[2][4];
#pragma unroll
            for (int mi = 0; mi < 4; mi++) {
                int off = (wm * 64 + mi * 16 + aRow) * SSTR + ks * 16 + aKh;
                ldsm4(aH[mi], baseAH + off);
                ldsm4(aL[mi], baseAH + off + TILE_HALF);
            }
#pragma unroll
            for (int njp = 0; njp < 2; njp++) {
                int off = (wn * 32 + njp * 16 + bNoff) * SSTR + ks * 16 + bKoff;
                ldsm4(bHr[njp], baseBH + off);
                ldsm4(bLr[njp], baseBH + off + TILE_HALF);
            }
#pragma unroll
            for (int mi = 0; mi < 4; mi++)
#pragma unroll
                for (int nj = 0; nj < 4; nj++) {
                    const int njp = nj >> 1, sub = nj & 1;
                    unsigned b0h = bHr[njp][sub * 2], b1h = bHr[njp][sub * 2 + 1];
                    unsigned b0l = bLr[njp][sub * 2], b1l = bLr[njp][sub * 2 + 1];
                    mma_bf16(acc[mi][nj], aH[mi], b0h, b1h);
                    mma_bf16(acc[mi][nj], aH[mi], b0l, b1l);
                    mma_bf16(acc[mi][nj], aL[mi], b0h, b1h);
                }
        }
        if (kt + 1 < nk) STORESM(buf ^ 1);
        __syncthreads();
    }

    // Epilogue
#pragma unroll
    for (int mi = 0; mi < 4; mi++) {
        const int r0 = m0 + wm * 64 + mi * 16 + (lane >> 2);
#pragma unroll
        for (int nj = 0; nj < 4; nj++) {
            const int c0 = n0 + wn * 32 + nj * 8 + (lane & 3) * 2;
            float b0 = 0.f, b1 = 0.f;
            if (bias) { b0 = bias[c0]; b1 = bias[c0 + 1]; }
            float2 v0 = make_float2(acc[mi][nj][0] + b0, acc[mi][nj][1] + b1);
            float2 v1 = make_float2(acc[mi][nj][2] + b0, acc[mi][nj][3] + b1);
            *(float2*)(C + (size_t)r0 * Nc + c0) = v0;
            *(float2*)(C + (size_t)(r0 + 8) * Nc + c0) = v1;
        }
    }
#undef LOADREGS
#undef STORESM
}

// ===========================================================================
// Fused attention per (b,h). K/V in smem; warps own 4-row groups.
// Softmax computed per row-pair, PV batched over 2 rows (5 LDS / 6 FMA).
// ===========================================================================
#define KSTR 97
#define SM_KS   (256 * KSTR)          // 24832
#define SM_VS   (256 * HDIM)          // 24576
#define SM_QS   (8 * 4 * HDIM)        // 3072
#define SM_SR   (8 * 512)             // 4096 (2 p-rows per warp)
#define ATT_SMEM_FLOATS (SM_KS + SM_VS + SM_QS + SM_SR)
#define ATT_SMEM_BYTES  (ATT_SMEM_FLOATS * 4)   // 226304 B

__global__ __launch_bounds__(256) void attn_kernel(
    const float* __restrict__ qkv, float* __restrict__ out)
{
    extern __shared__ float smf[];
    float* ks   = smf;                      // [256][97]
    float* vs   = ks + SM_KS;               // [256][96]
    float* qs   = vs + SM_VS;               // [8][4][96]
    float* srow = qs + SM_QS;               // [8][2][256]

    const int bh = blockIdx.x;
    const int b = bh >> 3, h = bh & 7;
    const int tid = threadIdx.x;
    const int w = tid >> 5, lane = tid & 31;
    const float scale = 0.1020620726159658f;   // 96^-0.5

    const size_t base = (size_t)b * NTOK * C3;

    // Stage K and V (rows 236..255 zero-filled)
    for (int idx = tid; idx < 256 * HDIM; idx += 256) {
        int m = idx / HDIM;
        int d = idx - m * HDIM;
        float kv = 0.f, vv = 0.f;
        if (m < NTOK) {
            const float* row = qkv + base + (size_t)m * C3 + h * HDIM + d;
            kv = row[CDIM];
            vv = row[2 * CDIM];
        }
        ks[m * KSTR + d] = kv;
        vs[m * HDIM + d] = vv;
    }
    __syncthreads();

    float* myq = qs + w * (4 * HDIM);
    float* myp = srow + w * 512;

    for (int g = w; g < 59; g += 8) {
        const int n0 = g * 4;

        for (int i = lane; i < 4 * HDIM; i += 32) {
            int r = i / HDIM;
            int d = i - r * HDIM;
            myq[i] = qkv[base + (size_t)(n0 + r) * C3 + h * HDIM + d];
        }
        __syncwarp();

        float acc[4][8];
#pragma unroll
        for (int r = 0; r < 4; r++)
#pragma unroll
            for (int j = 0; j < 8; j++) acc[r][j] = 0.f;

#pragma unroll 2
        for (int d = 0; d < HDIM; d++) {
            float q0 = myq[d];
            float q1 = myq[HDIM + d];
            float q2 = myq[2 * HDIM + d];
            float q3 = myq[3 * HDIM + d];
#pragma unroll
            for (int j = 0; j < 8; j++) {
                float kv = ks[(j * 32 + lane) * KSTR + d];
                acc[0][j] = fmaf(q0, kv, acc[0][j]);
                acc[1][j] = fmaf(q1, kv, acc[1][j]);
                acc[2][j] = fmaf(q2, kv, acc[2][j]);
                acc[3][j] = fmaf(q3, kv, acc[3][j]);
            }
        }

#pragma unroll 1
        for (int rp = 0; rp < 2; rp++) {
            float inv2[2];
#pragma unroll 1
            for (int rr = 0; rr < 2; rr++) {
                const int r = rp * 2 + rr;
                const int n = n0 + r;
                float* mys = myp + rr * 256;
#pragma unroll
                for (int j = 0; j < 8; j++)
                    mys[j * 32 + lane] = acc[r][j] * scale;
                __syncwarp();

                // block-wise edits (copy uses pre-bias values)
                if (n < S1C) {
                    if (lane < (S2C - S1C)) {
                        float cp = mys[S1C + lane];
                        mys[S2C + lane] = cp;
                        mys[S1C + lane] = cp - BIASV;
                    }
                } else if (n < S2C) {
                    if (lane < (NTOK - S2C)) mys[S2C + lane] -= BIASV;
                } else {
                    if (lane < (S2C - S1C)) mys[S1C + lane] -= BIASV;
                }
                __syncwarp();

                float vals[8];
                float vmax = -1e30f;
#pragma unroll
                for (int j = 0; j < 8; j++) {
                    int m = j * 32 + lane;
                    vals[j] = (m < NTOK) ? mys[m] : -1e30f;
                    vmax = fmaxf(vmax, vals[j]);
                }
#pragma unroll
                for (int o = 16; o > 0; o >>= 1)
                    vmax = fmaxf(vmax, __shfl_xor_sync(0xFFFFFFFFu, vmax, o));
                float ssum = 0.f;
#pragma unroll
                for (int j = 0; j < 8; j++) {
                    float e = expf(vals[j] - vmax);
                    ssum += e;
                    mys[j * 32 + lane] = e;
                }
#pragma unroll
                for (int o = 16; o > 0; o >>= 1)
                    ssum += __shfl_xor_sync(0xFFFFFFFFu, ssum, o);
                inv2[rr] = 1.f / ssum;
                __syncwarp();
            }

            // Batched 2-row PV: lane covers d = lane, +32, +64
            const float* pA = myp;
            const float* pB = myp + 256;
            float o00 = 0.f, o01 = 0.f, o02 = 0.f;
            float o10 = 0.f, o11 = 0.f, o12 = 0.f;
#pragma unroll 4
            for (int m = 0; m < NTOK; m++) {
                float v0 = vs[m * HDIM + lane];
                float v1 = vs[m * HDIM + lane + 32];
                float v2 = vs[m * HDIM + lane + 64];
                float p0 = pA[m];
                float p1 = pB[m];
                o00 = fmaf(p0, v0, o00); o01 = fmaf(p0, v1, o01); o02 = fmaf(p0, v2, o02);
                o10 = fmaf(p1, v0, o10); o11 = fmaf(p1, v1, o11); o12 = fmaf(p1, v2, o12);
            }
            {
                const int n = n0 + rp * 2;
                size_t ob = (size_t)(b * NTOK + n) * CDIM + h * HDIM + lane;
                out[ob]      = o00 * inv2[0];
                out[ob + 32] = o01 * inv2[0];
                out[ob + 64] = o02 * inv2[0];
                ob += CDIM;
                out[ob]      = o10 * inv2[1];
                out[ob + 32] = o11 * inv2[1];
                out[ob + 64] = o12 * inv2[1];
            }
            __syncwarp();
        }
    }
}

// ===========================================================================
// Launch
// ===========================================================================
extern "C" void kernel_launch(void* const* d_in, const int* in_sizes, int n_in,
                              void* d_out, int out_size)
{
    const float* x      = (const float*)d_in[0];   // [64,236,768]
    const float* qkv_w  = (const float*)d_in[1];   // [2304,768]
    const float* proj_w = (const float*)d_in[2];   // [768,768]
    const float* proj_b = (const float*)d_in[3];   // [768]
    float* out = (float*)d_out;                    // [64,236,768]

    float* qkv_buf = nullptr;
    float* att_buf = nullptr;
    cudaGetSymbolAddress((void**)&qkv_buf, g_qkv);
    cudaGetSymbolAddress((void**)&att_buf, g_att);

    cudaFuncSetAttribute(gemm_bf16x3,
                         cudaFuncAttributeMaxDynamicSharedMemorySize,
                         GEMM_SMEM_BYTES);
    cudaFuncSetAttribute(attn_kernel,
                         cudaFuncAttributeMaxDynamicSharedMemorySize,
                         ATT_SMEM_BYTES);

    // 1) QKV projection: [15104,768] @ [2304,768]^T -> [15104,2304]
    {
        dim3 grid(C3 / GBN, MROWS / GBM);   // (18, 118)
        gemm_bf16x3<<<grid, 256, GEMM_SMEM_BYTES>>>(x, qkv_w, nullptr, qkv_buf,
                                                    MROWS, C3, CDIM);
    }

    // 2) Fused attention: 512 CTAs, one per (b,h)
    attn_kernel<<<BATCH * HEADS, 256, ATT_SMEM_BYTES>>>(qkv_buf, att_buf);

    // 3) Output projection: [15104,768] @ [768,768]^T + bias -> [15104,768]
    {
        dim3 grid(CDIM / GBN, MROWS / GBM); // (6, 118)
        gemm_bf16x3<<<grid, 256, GEMM_SMEM_BYTES>>>(att_buf, proj_w, proj_b, out,
                                                    MROWS, CDIM, CDIM);
    }
}

// round 4
// speedup vs baseline: 1.9782x; 1.1298x over previous
#include <cuda_runtime.h>
#include <cuda_bf16.h>
#include <math.h>

// Problem constants
#define BATCH   64
#define NTOK    236
#define CDIM    768
#define HEADS   8
#define HDIM    96
#define C3      2304
#define S1C     196
#define S2C     216
#define BIASV   100.0f
#define MROWS   (BATCH * NTOK)   // 15104

// Scratch (device globals; no allocation allowed)
__device__ float g_qkv[(size_t)MROWS * C3];   // [15104, 2304]
__device__ float g_att[(size_t)MROWS * CDIM]; // [15104, 768]

// ===========================================================================
// TF32 tensor-core GEMM:  C[m,n] = sum_k A[m,k] * W[n,k]  (+ bias[n])
// Block 128x256x32, 8 warps (2m x 4n), warp tile 64x64. cp.async 3-stage.
// ===========================================================================
#define GBM 128
#define GBN 256
#define GBK 32
#define NSTAGE 3
#define A_TILE_B 16384                 // 128 rows * 8 chunks * 16B
#define B_TILE_B 32768                 // 256 rows * 8 chunks * 16B
#define STAGE_B  (A_TILE_B + B_TILE_B) // 49152
#define GEMM_SMEM_BYTES (NSTAGE * STAGE_B)   // 147456

__device__ __forceinline__ void cp16(unsigned dst, const void* src) {
    asm volatile("cp.async.cg.shared.global [%0], [%1], 16;\n" :: "r"(dst), "l"(src));
}
__device__ __forceinline__ void cp_commit() {
    asm volatile("cp.async.commit_group;\n" ::);
}
__device__ __forceinline__ void cp_wait1() {
    asm volatile("cp.async.wait_group 1;\n" ::);
}

__device__ __forceinline__ void ldsm4(unsigned* r, unsigned addr) {
    asm volatile("ldmatrix.sync.aligned.m8n8.x4.shared.b16 {%0,%1,%2,%3}, [%4];\n"
        : "=r"(r[0]), "=r"(r[1]), "=r"(r[2]), "=r"(r[3]) : "r"(addr));
}

__device__ __forceinline__ unsigned f2tf(unsigned x) {
    unsigned y;
    asm volatile("cvt.rna.tf32.f32 %0, %1;\n" : "=r"(y) : "r"(x));
    return y;
}

__device__ __forceinline__ void mma_tf32(float* c, const unsigned* a,
                                         unsigned b0, unsigned b1) {
    asm volatile(
        "mma.sync.aligned.m16n8k8.row.col.f32.tf32.tf32.f32 "
        "{%0,%1,%2,%3}, {%4,%5,%6,%7}, {%8,%9}, {%0,%1,%2,%3};\n"
        : "+f"(c[0]), "+f"(c[1]), "+f"(c[2]), "+f"(c[3])
        : "r"(a[0]), "r"(a[1]), "r"(a[2]), "r"(a[3]), "r"(b0), "r"(b1));
}

// swizzled byte offset of 16B chunk (row, c) inside a tile with 8 chunks/row
__device__ __forceinline__ unsigned swz(int row, int c) {
    return (unsigned)((row * 8 + (c ^ (row & 7))) * 16);
}

__global__ __launch_bounds__(256, 1) void gemm_tf32(
    const float* __restrict__ A, const float* __restrict__ W,
    const float* __restrict__ bias, float* __restrict__ C,
    int M, int Nc, int K)
{
    extern __shared__ char smc[];
    const unsigned smem_u = (unsigned)__cvta_generic_to_shared(smc);

    const int tid = threadIdx.x;
    const int lane = tid & 31, wid = tid >> 5;
    const int wm = wid & 1, wn = wid >> 1;       // 2 x 4 warp grid
    const int m0 = blockIdx.y * GBM, n0 = blockIdx.x * GBN;

    // staging mapping
    const int ar = tid >> 1;                     // A row 0..127
    const int ac = (tid & 1) * 4;                // A chunk group 0 / 4
    const float* agp = A + (size_t)(m0 + ar) * K + ac * 4;
    const float* bgp = W + (size_t)(n0 + tid) * K;   // B row = tid
    unsigned aoff[4], boff[8];
#pragma unroll
    for (int q = 0; q < 4; q++) aoff[q] = swz(ar, ac + q);
#pragma unroll
    for (int q = 0; q < 8; q++) boff[q] = A_TILE_B + swz(tid, q);

#define ISSUE_STAGE(KT) do {                                                 \
    unsigned sb = smem_u + ((KT) % NSTAGE) * STAGE_B;                        \
    const float* ag = agp + (KT) * GBK;                                      \
    const float* bg = bgp + (KT) * GBK;                                      \
    _Pragma("unroll")                                                        \
    for (int q = 0; q < 4; q++) cp16(sb + aoff[q], ag + q * 4);              \
    _Pragma("unroll")                                                        \
    for (int q = 0; q < 8; q++) cp16(sb + boff[q], bg + q * 4);              \
} while (0)

    // ldmatrix per-lane row components
    const int t8 = (lane >> 3) & 1;
    const int t16 = lane >> 4;
    const int rr = lane & 7;
    const int rowA = wm * 64 + t8 * 8 + rr;       // + mi*16
    const int rowB = wn * 64 + t16 * 8 + rr;      // + njp*16

    float acc[4][8][4];
#pragma unroll
    for (int i = 0; i < 4; i++)
#pragma unroll
        for (int j = 0; j < 8; j++)
#pragma unroll
            for (int q = 0; q < 4; q++) acc[i][j][q] = 0.f;

    ISSUE_STAGE(0); cp_commit();
    ISSUE_STAGE(1); cp_commit();

    const int nk = K / GBK;
    for (int kt = 0; kt < nk; kt++) {
        cp_wait1();
        __syncthreads();
        if (kt + 2 < nk) { ISSUE_STAGE(kt + 2); }
        cp_commit();

        const unsigned sa = smem_u + (kt % NSTAGE) * STAGE_B;
        const unsigned sbb = sa + A_TILE_B;
#pragma unroll
        for (int ks = 0; ks < 4; ks++) {
            const int ca = 2 * ks + t16;          // A chunk
            const int cb = 2 * ks + t8;           // B chunk
            unsigned af[4][4], bf[4][4];
#pragma unroll
            for (int mi = 0; mi < 4; mi++) {
                int row = rowA + mi * 16;
                ldsm4(af[mi], sa + (unsigned)((row * 8 + (ca ^ (row & 7))) * 16));
#pragma unroll
                for (int q = 0; q < 4; q++) af[mi][q] = f2tf(af[mi][q]);
            }
#pragma unroll
            for (int njp = 0; njp < 4; njp++) {
                int row = rowB + njp * 16;
                ldsm4(bf[njp], sbb + (unsigned)((row * 8 + (cb ^ (row & 7))) * 16));
#pragma unroll
                for (int q = 0; q < 4; q++) bf[njp][q] = f2tf(bf[njp][q]);
            }
#pragma unroll
            for (int mi = 0; mi < 4; mi++)
#pragma unroll
                for (int njp = 0; njp < 4; njp++) {
                    mma_tf32(acc[mi][njp * 2],     af[mi], bf[njp][0], bf[njp][1]);
                    mma_tf32(acc[mi][njp * 2 + 1], af[mi], bf[njp][2], bf[njp][3]);
                }
        }
    }

    // Epilogue
#pragma unroll
    for (int mi = 0; mi < 4; mi++) {
        const int r0 = m0 + wm * 64 + mi * 16 + (lane >> 2);
#pragma unroll
        for (int nj = 0; nj < 8; nj++) {
            const int c0 = n0 + wn * 64 + nj * 8 + (lane & 3) * 2;
            float b0 = 0.f, b1 = 0.f;
            if (bias) { b0 = bias[c0]; b1 = bias[c0 + 1]; }
            *(float2*)(C + (size_t)r0 * Nc + c0) =
                make_float2(acc[mi][nj][0] + b0, acc[mi][nj][1] + b1);
            *(float2*)(C + (size_t)(r0 + 8) * Nc + c0) =
                make_float2(acc[mi][nj][2] + b0, acc[mi][nj][3] + b1);
        }
    }
#undef ISSUE_STAGE
}

// ===========================================================================
// Fused attention per (b,h). K,V stored TRANSPOSED in smem: ksT[d][m],
// vsT[d][m]. Scores kept in registers (lane owns cols 4l..4l+3 and
// 128+4l..128+4l+3); block edits + softmax fully in registers via shuffles.
// ===========================================================================
#define KTS 240                       // ksT row stride (floats)
#define VTS 244                       // vsT row stride (floats)
#define SM_KT (HDIM * KTS)            // 23040
#define SM_VT (HDIM * VTS)            // 23424
#define SM_Q  (8 * 4 * HDIM)          // 3072
#define SM_P  (8 * 4 * KTS)           // 7680
#define ATT_SMEM_FLOATS (SM_KT + SM_VT + SM_Q + SM_P)
#define ATT_SMEM_BYTES  (ATT_SMEM_FLOATS * 4)   // 228864

__global__ __launch_bounds__(256) void attn_kernel(
    const float* __restrict__ qkv, float* __restrict__ out)
{
    extern __shared__ float smf[];
    float* ksT = smf;                  // [96][240]
    float* vsT = ksT + SM_KT;          // [96][244]
    float* qs  = vsT + SM_VT;          // [8][4][96]
    float* ps  = qs + SM_Q;            // [8][4][240]

    const int bh = blockIdx.x;
    const int b = bh >> 3, h = bh & 7;
    const int tid = threadIdx.x;
    const int w = tid >> 5, lane = tid & 31;
    const float scale = 0.1020620726159658f;   // 96^-0.5

    const size_t base = (size_t)b * NTOK * C3;

    // Stage K,V transposed. idx -> (chunk c of 4 d-values, m)
    for (int idx = tid; idx < 24 * 256; idx += 256) {
        const int c = idx >> 8;
        const int m = idx & 255;
        if (m < 240) {
            float4 kv = make_float4(0.f, 0.f, 0.f, 0.f);
            float4 vv = kv;
            if (m < NTOK) {
                const float* row = qkv + base + (size_t)m * C3 + h * HDIM + c * 4;
                kv = *(const float4*)(row + CDIM);
                vv = *(const float4*)(row + 2 * CDIM);
            }
            const int d = c * 4;
            ksT[(d + 0) * KTS + m] = kv.x;
            ksT[(d + 1) * KTS + m] = kv.y;
            ksT[(d + 2) * KTS + m] = kv.z;
            ksT[(d + 3) * KTS + m] = kv.w;
            vsT[(d + 0) * VTS + m] = vv.x;
            vsT[(d + 1) * VTS + m] = vv.y;
            vsT[(d + 2) * VTS + m] = vv.z;
            vsT[(d + 3) * VTS + m] = vv.w;
        }
    }
    __syncthreads();

    float* myq = qs + w * (4 * HDIM);
    float* myp = ps + w * (4 * KTS);
    const int c2 = (lane < 28) ? (128 + 4 * lane) : 128;

    for (int g = w; g < 59; g += 8) {
        const int n0 = g * 4;

        // stage 4 q rows, scale folded in
        for (int i = lane; i < HDIM; i += 32) {
#pragma unroll
            for (int r = 0; r < 4; r++)
                myq[r * HDIM + i] =
                    qkv[base + (size_t)(n0 + r) * C3 + h * HDIM + i] * scale;
        }
        __syncwarp();

        // ---- QK^T ----
        float acc[4][8];
#pragma unroll
        for (int r = 0; r < 4; r++)
#pragma unroll
            for (int j = 0; j < 8; j++) acc[r][j] = 0.f;

        for (int d4 = 0; d4 < 24; d4++) {
            float4 q4[4];
#pragma unroll
            for (int r = 0; r < 4; r++)
                q4[r] = *(const float4*)&myq[r * HDIM + d4 * 4];
#pragma unroll
            for (int dd = 0; dd < 4; dd++) {
                const int d = d4 * 4 + dd;
                const float4 k1 = *(const float4*)&ksT[d * KTS + 4 * lane];
                const float4 k2 = *(const float4*)&ksT[d * KTS + c2];
                const float qr[4] = {
                    dd == 0 ? q4[0].x : dd == 1 ? q4[0].y : dd == 2 ? q4[0].z : q4[0].w,
                    dd == 0 ? q4[1].x : dd == 1 ? q4[1].y : dd == 2 ? q4[1].z : q4[1].w,
                    dd == 0 ? q4[2].x : dd == 1 ? q4[2].y : dd == 2 ? q4[2].z : q4[2].w,
                    dd == 0 ? q4[3].x : dd == 1 ? q4[3].y : dd == 2 ? q4[3].z : q4[3].w };
#pragma unroll
                for (int r = 0; r < 4; r++) {
                    acc[r][0] = fmaf(qr[r], k1.x, acc[r][0]);
                    acc[r][1] = fmaf(qr[r], k1.y, acc[r][1]);
                    acc[r][2] = fmaf(qr[r], k1.z, acc[r][2]);
                    acc[r][3] = fmaf(qr[r], k1.w, acc[r][3]);
                    acc[r][4] = fmaf(qr[r], k2.x, acc[r][4]);
                    acc[r][5] = fmaf(qr[r], k2.y, acc[r][5]);
                    acc[r][6] = fmaf(qr[r], k2.z, acc[r][6]);
                    acc[r][7] = fmaf(qr[r], k2.w, acc[r][7]);
                }
            }
        }

        // ---- edits + softmax (registers), store p ----
        float inv[4];
#pragma unroll
        for (int r = 0; r < 4; r++) {
            const int n = n0 + r;
            float s1[4], s2[4];
#pragma unroll
            for (int i = 0; i < 4; i++) { s1[i] = acc[r][i]; s2[i] = acc[r][4 + i]; }

            // copy source (cols 196..215 live in lanes 17..21; dst lanes 22..26)
            float src[4];
#pragma unroll
            for (int i = 0; i < 4; i++)
                src[i] = __shfl_sync(0xFFFFFFFFu, s2[i], (lane - 5) & 31);

            if (n < S1C) {
                if (lane >= 22 && lane <= 26) {
#pragma unroll
                    for (int i = 0; i < 4; i++) s2[i] = src[i];
                }
                if (lane >= 17 && lane <= 21) {
#pragma unroll
                    for (int i = 0; i < 4; i++) s2[i] -= BIASV;
                }
            } else if (n < S2C) {
                if (lane >= 22 && lane <= 26) {
#pragma unroll
                    for (int i = 0; i < 4; i++) s2[i] -= BIASV;
                }
            } else {
                if (lane >= 17 && lane <= 21) {
#pragma unroll
                    for (int i = 0; i < 4; i++) s2[i] -= BIASV;
                }
            }
            if (lane >= 27) {
#pragma unroll
                for (int i = 0; i < 4; i++) s2[i] = -1e30f;
            }

            float vmax = s1[0];
#pragma unroll
            for (int i = 1; i < 4; i++) vmax = fmaxf(vmax, s1[i]);
#pragma unroll
            for (int i = 0; i < 4; i++) vmax = fmaxf(vmax, s2[i]);
#pragma unroll
            for (int o = 16; o > 0; o >>= 1)
                vmax = fmaxf(vmax, __shfl_xor_sync(0xFFFFFFFFu, vmax, o));

            float e1[4], e2[4], ssum = 0.f;
#pragma unroll
            for (int i = 0; i < 4; i++) { e1[i] = __expf(s1[i] - vmax); ssum += e1[i]; }
#pragma unroll
            for (int i = 0; i < 4; i++) { e2[i] = __expf(s2[i] - vmax); ssum += e2[i]; }
#pragma unroll
            for (int o = 16; o > 0; o >>= 1)
                ssum += __shfl_xor_sync(0xFFFFFFFFu, ssum, o);
            inv[r] = 1.f / ssum;

            *(float4*)&myp[r * KTS + 4 * lane] = make_float4(e1[0], e1[1], e1[2], e1[3]);
            if (lane < 28)
                *(float4*)&myp[r * KTS + 128 + 4 * lane] =
                    make_float4(e2[0], e2[1], e2[2], e2[3]);
        }
        __syncwarp();

        // ---- PV ----
        float o0[4], o1[4], o2[4];
#pragma unroll
        for (int r = 0; r < 4; r++) { o0[r] = 0.f; o1[r] = 0.f; o2[r] = 0.f; }

        const float* vrow0 = vsT + lane * VTS;
        const float* vrow1 = vsT + (lane + 32) * VTS;
        const float* vrow2 = vsT + (lane + 64) * VTS;

#pragma unroll 2
        for (int m4 = 0; m4 < 60; m4++) {
            const int m = m4 * 4;
            float4 p4[4];
#pragma unroll
            for (int r = 0; r < 4; r++)
                p4[r] = *(const float4*)&myp[r * KTS + m];
            const float4 v0 = *(const float4*)(vrow0 + m);
            const float4 v1 = *(const float4*)(vrow1 + m);
            const float4 v2 = *(const float4*)(vrow2 + m);
#pragma unroll
            for (int r = 0; r < 4; r++) {
                o0[r] = fmaf(p4[r].x, v0.x, o0[r]);
                o0[r] = fmaf(p4[r].y, v0.y, o0[r]);
                o0[r] = fmaf(p4[r].z, v0.z, o0[r]);
                o0[r] = fmaf(p4[r].w, v0.w, o0[r]);
                o1[r] = fmaf(p4[r].x, v1.x, o1[r]);
                o1[r] = fmaf(p4[r].y, v1.y, o1[r]);
                o1[r] = fmaf(p4[r].z, v1.z, o1[r]);
                o1[r] = fmaf(p4[r].w, v1.w, o1[r]);
                o2[r] = fmaf(p4[r].x, v2.x, o2[r]);
                o2[r] = fmaf(p4[r].y, v2.y, o2[r]);
                o2[r] = fmaf(p4[r].z, v2.z, o2[r]);
                o2[r] = fmaf(p4[r].w, v2.w, o2[r]);
            }
        }

#pragma unroll
        for (int r = 0; r < 4; r++) {
            size_t ob = (size_t)(b * NTOK + n0 + r) * CDIM + h * HDIM + lane;
            out[ob]      = o0[r] * inv[r];
            out[ob + 32] = o1[r] * inv[r];
            out[ob + 64] = o2[r] * inv[r];
        }
        __syncwarp();
    }
}

// ===========================================================================
// Launch
// ===========================================================================
extern "C" void kernel_launch(void* const* d_in, const int* in_sizes, int n_in,
                              void* d_out, int out_size)
{
    const float* x      = (const float*)d_in[0];   // [64,236,768]
    const float* qkv_w  = (const float*)d_in[1];   // [2304,768]
    const float* proj_w = (const float*)d_in[2];   // [768,768]
    const float* proj_b = (const float*)d_in[3];   // [768]
    float* out = (float*)d_out;                    // [64,236,768]

    float* qkv_buf = nullptr;
    float* att_buf = nullptr;
    cudaGetSymbolAddress((void**)&qkv_buf, g_qkv);
    cudaGetSymbolAddress((void**)&att_buf, g_att);

    cudaFuncSetAttribute(gemm_tf32,
                         cudaFuncAttributeMaxDynamicSharedMemorySize,
                         GEMM_SMEM_BYTES);
    cudaFuncSetAttribute(attn_kernel,
                         cudaFuncAttributeMaxDynamicSharedMemorySize,
                         ATT_SMEM_BYTES);

    // 1) QKV projection: [15104,768] @ [2304,768]^T -> [15104,2304]
    {
        dim3 grid(C3 / GBN, MROWS / GBM);   // (9, 118)
        gemm_tf32<<<grid, 256, GEMM_SMEM_BYTES>>>(x, qkv_w, nullptr, qkv_buf,
                                                  MROWS, C3, CDIM);
    }

    // 2) Fused attention: 512 CTAs, one per (b,h)
    attn_kernel<<<BATCH * HEADS, 256, ATT_SMEM_BYTES>>>(qkv_buf, att_buf);

    // 3) Output projection: [15104,768] @ [768,768]^T + bias -> [15104,768]
    {
        dim3 grid(CDIM / GBN, MROWS / GBM); // (3, 118)
        gemm_tf32<<<grid, 256, GEMM_SMEM_BYTES>>>(att_buf, proj_w, proj_b, out,
                                                  MROWS, CDIM, CDIM);
    }
}

// round 5
// speedup vs baseline: 2.0127x; 1.0175x over previous
#include <cuda_runtime.h>
#include <cuda_bf16.h>
#include <math.h>

// Problem constants
#define BATCH   64
#define NTOK    236
#define CDIM    768
#define HEADS   8
#define HDIM    96
#define C3      2304
#define S1C     196
#define S2C     216
#define BIASV   100.0f
#define MROWS   (BATCH * NTOK)   // 15104

// Scratch (device globals; no allocation allowed)
__device__ float g_qkv[(size_t)MROWS * C3];   // [15104, 2304] fp32
__device__ float g_att[(size_t)MROWS * CDIM]; // [15104, 768]  tf32-rounded
__device__ float g_xc [(size_t)MROWS * CDIM]; // x, tf32-rounded
__device__ float g_wqc[(size_t)C3 * CDIM];    // qkv_w, tf32-rounded
__device__ float g_wpc[(size_t)CDIM * CDIM];  // proj_w, tf32-rounded

__device__ __forceinline__ unsigned f2tf(unsigned x) {
    unsigned y;
    asm volatile("cvt.rna.tf32.f32 %0, %1;\n" : "=r"(y) : "r"(x));
    return y;
}
__device__ __forceinline__ float f2tf_f(float x) {
    return __uint_as_float(f2tf(__float_as_uint(x)));
}

// ---------------------------------------------------------------------------
// Elementwise fp32 -> tf32(rna) pre-conversion (vectorized)
// ---------------------------------------------------------------------------
__global__ __launch_bounds__(256) void cvt_tf32_kernel(
    const float* __restrict__ in, float* __restrict__ out, int n4)
{
    int i = blockIdx.x * blockDim.x + threadIdx.x;
    if (i < n4) {
        float4 v = ((const float4*)in)[i];
        v.x = f2tf_f(v.x); v.y = f2tf_f(v.y);
        v.z = f2tf_f(v.z); v.w = f2tf_f(v.w);
        ((float4*)out)[i] = v;
    }
}

// ===========================================================================
// TF32 tensor-core GEMM:  C[m,n] = sum_k A[m,k] * W[n,k]  (+ bias[n])
// A and W must already be tf32-rounded. Block 128x256x32, 8 warps (2x4),
// warp tile 64x64, cp.async 3-stage pipeline, swizzled smem.
// ===========================================================================
#define GBM 128
#define GBN 256
#define GBK 32
#define NSTAGE 3
#define A_TILE_B 16384                 // 128 rows * 8 chunks * 16B
#define B_TILE_B 32768                 // 256 rows * 8 chunks * 16B
#define STAGE_B  (A_TILE_B + B_TILE_B) // 49152
#define GEMM_SMEM_BYTES (NSTAGE * STAGE_B)   // 147456

__device__ __forceinline__ void cp16(unsigned dst, const void* src) {
    asm volatile("cp.async.cg.shared.global [%0], [%1], 16;\n" :: "r"(dst), "l"(src));
}
__device__ __forceinline__ void cp_commit() {
    asm volatile("cp.async.commit_group;\n" ::);
}
__device__ __forceinline__ void cp_wait1() {
    asm volatile("cp.async.wait_group 1;\n" ::);
}

__device__ __forceinline__ void ldsm4(unsigned* r, unsigned addr) {
    asm volatile("ldmatrix.sync.aligned.m8n8.x4.shared.b16 {%0,%1,%2,%3}, [%4];\n"
        : "=r"(r[0]), "=r"(r[1]), "=r"(r[2]), "=r"(r[3]) : "r"(addr));
}

__device__ __forceinline__ void mma_tf32(float* c, const unsigned* a,
                                         unsigned b0, unsigned b1) {
    asm volatile(
        "mma.sync.aligned.m16n8k8.row.col.f32.tf32.tf32.f32 "
        "{%0,%1,%2,%3}, {%4,%5,%6,%7}, {%8,%9}, {%0,%1,%2,%3};\n"
        : "+f"(c[0]), "+f"(c[1]), "+f"(c[2]), "+f"(c[3])
        : "r"(a[0]), "r"(a[1]), "r"(a[2]), "r"(a[3]), "r"(b0), "r"(b1));
}

__device__ __forceinline__ unsigned swz(int row, int c) {
    return (unsigned)((row * 8 + (c ^ (row & 7))) * 16);
}

__global__ __launch_bounds__(256, 1) void gemm_tf32(
    const float* __restrict__ A, const float* __restrict__ W,
    const float* __restrict__ bias, float* __restrict__ C,
    int M, int Nc, int K)
{
    extern __shared__ char smc[];
    const unsigned smem_u = (unsigned)__cvta_generic_to_shared(smc);

    const int tid = threadIdx.x;
    const int lane = tid & 31, wid = tid >> 5;
    const int wm = wid & 1, wn = wid >> 1;       // 2 x 4 warp grid
    const int m0 = blockIdx.y * GBM, n0 = blockIdx.x * GBN;

    // staging mapping
    const int ar = tid >> 1;                     // A row 0..127
    const int ac = (tid & 1) * 4;                // A chunk group 0 / 4
    const float* agp = A + (size_t)(m0 + ar) * K + ac * 4;
    const float* bgp = W + (size_t)(n0 + tid) * K;   // B row = tid
    unsigned aoff[4], boff[8];
#pragma unroll
    for (int q = 0; q < 4; q++) aoff[q] = swz(ar, ac + q);
#pragma unroll
    for (int q = 0; q < 8; q++) boff[q] = A_TILE_B + swz(tid, q);

#define ISSUE_STAGE(KT) do {                                                 \
    unsigned sb = smem_u + ((KT) % NSTAGE) * STAGE_B;                        \
    const float* ag = agp + (KT) * GBK;                                      \
    const float* bg = bgp + (KT) * GBK;                                      \
    _Pragma("unroll")                                                        \
    for (int q = 0; q < 4; q++) cp16(sb + aoff[q], ag + q * 4);              \
    _Pragma("unroll")                                                        \
    for (int q = 0; q < 8; q++) cp16(sb + boff[q], bg + q * 4);              \
} while (0)

    // ldmatrix per-lane row components
    const int t8 = (lane >> 3) & 1;
    const int t16 = lane >> 4;
    const int rr = lane & 7;
    const int rowA = wm * 64 + t8 * 8 + rr;       // + mi*16
    const int rowB = wn * 64 + t16 * 8 + rr;      // + njp*16

    float acc[4][8][4];
#pragma unroll
    for (int i = 0; i < 4; i++)
#pragma unroll
        for (int j = 0; j < 8; j++)
#pragma unroll
            for (int q = 0; q < 4; q++) acc[i][j][q] = 0.f;

    ISSUE_STAGE(0); cp_commit();
    ISSUE_STAGE(1); cp_commit();

    const int nk = K / GBK;
    for (int kt = 0; kt < nk; kt++) {
        cp_wait1();
        __syncthreads();
        if (kt + 2 < nk) { ISSUE_STAGE(kt + 2); }
        cp_commit();

        const unsigned sa = smem_u + (kt % NSTAGE) * STAGE_B;
        const unsigned sbb = sa + A_TILE_B;
#pragma unroll
        for (int ks = 0; ks < 4; ks++) {
            const int ca = 2 * ks + t16;          // A chunk
            const int cb = 2 * ks + t8;           // B chunk
            unsigned af[4][4], bf[4][4];
#pragma unroll
            for (int mi = 0; mi < 4; mi++) {
                int row = rowA + mi * 16;
                ldsm4(af[mi], sa + (unsigned)((row * 8 + (ca ^ (row & 7))) * 16));
            }
#pragma unroll
            for (int njp = 0; njp < 4; njp++) {
                int row = rowB + njp * 16;
                ldsm4(bf[njp], sbb + (unsigned)((row * 8 + (cb ^ (row & 7))) * 16));
            }
#pragma unroll
            for (int mi = 0; mi < 4; mi++)
#pragma unroll
                for (int njp = 0; njp < 4; njp++) {
                    mma_tf32(acc[mi][njp * 2],     af[mi], bf[njp][0], bf[njp][1]);
                    mma_tf32(acc[mi][njp * 2 + 1], af[mi], bf[njp][2], bf[njp][3]);
                }
        }
    }

    // Epilogue
#pragma unroll
    for (int mi = 0; mi < 4; mi++) {
        const int r0 = m0 + wm * 64 + mi * 16 + (lane >> 2);
#pragma unroll
        for (int nj = 0; nj < 8; nj++) {
            const int c0 = n0 + wn * 64 + nj * 8 + (lane & 3) * 2;
            float b0 = 0.f, b1 = 0.f;
            if (bias) { b0 = bias[c0]; b1 = bias[c0 + 1]; }
            *(float2*)(C + (size_t)r0 * Nc + c0) =
                make_float2(acc[mi][nj][0] + b0, acc[mi][nj][1] + b1);
            *(float2*)(C + (size_t)(r0 + 8) * Nc + c0) =
                make_float2(acc[mi][nj][2] + b0, acc[mi][nj][3] + b1);
        }
    }
#undef ISSUE_STAGE
}

// ===========================================================================
// Fused attention per (b,h). K,V stored TRANSPOSED in smem: ksT[d][m],
// vsT[d][m]. Scores kept in registers; block edits + softmax via shuffles.
// Output written tf32-rounded (feeds the proj GEMM directly).
// ===========================================================================
#define KTS 240                       // ksT row stride (floats)
#define VTS 244                       // vsT row stride (floats)
#define SM_KT (HDIM * KTS)            // 23040
#define SM_VT (HDIM * VTS)            // 23424
#define SM_Q  (8 * 4 * HDIM)          // 3072
#define SM_P  (8 * 4 * KTS)           // 7680
#define ATT_SMEM_FLOATS (SM_KT + SM_VT + SM_Q + SM_P)
#define ATT_SMEM_BYTES  (ATT_SMEM_FLOATS * 4)   // 228864

__global__ __launch_bounds__(256) void attn_kernel(
    const float* __restrict__ qkv, float* __restrict__ out)
{
    extern __shared__ float smf[];
    float* ksT = smf;                  // [96][240]
    float* vsT = ksT + SM_KT;          // [96][244]
    float* qs  = vsT + SM_VT;          // [8][4][96]
    float* ps  = qs + SM_Q;            // [8][4][240]

    const int bh = blockIdx.x;
    const int b = bh >> 3, h = bh & 7;
    const int tid = threadIdx.x;
    const int w = tid >> 5, lane = tid & 31;
    const float scale = 0.1020620726159658f;   // 96^-0.5

    const size_t base = (size_t)b * NTOK * C3;

    // Stage K,V transposed. idx -> (chunk c of 4 d-values, m)
    for (int idx = tid; idx < 24 * 256; idx += 256) {
        const int c = idx >> 8;
        const int m = idx & 255;
        if (m < 240) {
            float4 kv = make_float4(0.f, 0.f, 0.f, 0.f);
            float4 vv = kv;
            if (m < NTOK) {
                const float* row = qkv + base + (size_t)m * C3 + h * HDIM + c * 4;
                kv = *(const float4*)(row + CDIM);
                vv = *(const float4*)(row + 2 * CDIM);
            }
            const int d = c * 4;
            ksT[(d + 0) * KTS + m] = kv.x;
            ksT[(d + 1) * KTS + m] = kv.y;
            ksT[(d + 2) * KTS + m] = kv.z;
            ksT[(d + 3) * KTS + m] = kv.w;
            vsT[(d + 0) * VTS + m] = vv.x;
            vsT[(d + 1) * VTS + m] = vv.y;
            vsT[(d + 2) * VTS + m] = vv.z;
            vsT[(d + 3) * VTS + m] = vv.w;
        }
    }
    __syncthreads();

    float* myq = qs + w * (4 * HDIM);
    float* myp = ps + w * (4 * KTS);
    const int c2 = (lane < 28) ? (128 + 4 * lane) : 128;

    for (int g = w; g < 59; g += 8) {
        const int n0 = g * 4;

        // stage 4 q rows, scale folded in
        for (int i = lane; i < HDIM; i += 32) {
#pragma unroll
            for (int r = 0; r < 4; r++)
                myq[r * HDIM + i] =
                    qkv[base + (size_t)(n0 + r) * C3 + h * HDIM + i] * scale;
        }
        __syncwarp();

        // ---- QK^T ----
        float acc[4][8];
#pragma unroll
        for (int r = 0; r < 4; r++)
#pragma unroll
            for (int j = 0; j < 8; j++) acc[r][j] = 0.f;

        for (int d4 = 0; d4 < 24; d4++) {
            float4 q4[4];
#pragma unroll
            for (int r = 0; r < 4; r++)
                q4[r] = *(const float4*)&myq[r * HDIM + d4 * 4];
#pragma unroll
            for (int dd = 0; dd < 4; dd++) {
                const int d = d4 * 4 + dd;
                const float4 k1 = *(const float4*)&ksT[d * KTS + 4 * lane];
                const float4 k2 = *(const float4*)&ksT[d * KTS + c2];
                const float qr[4] = {
                    dd == 0 ? q4[0].x : dd == 1 ? q4[0].y : dd == 2 ? q4[0].z : q4[0].w,
                    dd == 0 ? q4[1].x : dd == 1 ? q4[1].y : dd == 2 ? q4[1].z : q4[1].w,
                    dd == 0 ? q4[2].x : dd == 1 ? q4[2].y : dd == 2 ? q4[2].z : q4[2].w,
                    dd == 0 ? q4[3].x : dd == 1 ? q4[3].y : dd == 2 ? q4[3].z : q4[3].w };
#pragma unroll
                for (int r = 0; r < 4; r++) {
                    acc[r][0] = fmaf(qr[r], k1.x, acc[r][0]);
                    acc[r][1] = fmaf(qr[r], k1.y, acc[r][1]);
                    acc[r][2] = fmaf(qr[r], k1.z, acc[r][2]);
                    acc[r][3] = fmaf(qr[r], k1.w, acc[r][3]);
                    acc[r][4] = fmaf(qr[r], k2.x, acc[r][4]);
                    acc[r][5] = fmaf(qr[r], k2.y, acc[r][5]);
                    acc[r][6] = fmaf(qr[r], k2.z, acc[r][6]);
                    acc[r][7] = fmaf(qr[r], k2.w, acc[r][7]);
                }
            }
        }

        // ---- edits + softmax (registers), store p ----
        float inv[4];
#pragma unroll
        for (int r = 0; r < 4; r++) {
            const int n = n0 + r;
            float s1[4], s2[4];
#pragma unroll
            for (int i = 0; i < 4; i++) { s1[i] = acc[r][i]; s2[i] = acc[r][4 + i]; }

            // copy source (cols 196..215 live in lanes 17..21; dst lanes 22..26)
            float src[4];
#pragma unroll
            for (int i = 0; i < 4; i++)
                src[i] = __shfl_sync(0xFFFFFFFFu, s2[i], (lane - 5) & 31);

            if (n < S1C) {
                if (lane >= 22 && lane <= 26) {
#pragma unroll
                    for (int i = 0; i < 4; i++) s2[i] = src[i];
                }
                if (lane >= 17 && lane <= 21) {
#pragma unroll
                    for (int i = 0; i < 4; i++) s2[i] -= BIASV;
                }
            } else if (n < S2C) {
                if (lane >= 22 && lane <= 26) {
#pragma unroll
                    for (int i = 0; i < 4; i++) s2[i] -= BIASV;
                }
            } else {
                if (lane >= 17 && lane <= 21) {
#pragma unroll
                    for (int i = 0; i < 4; i++) s2[i] -= BIASV;
                }
            }
            if (lane >= 27) {
#pragma unroll
                for (int i = 0; i < 4; i++) s2[i] = -1e30f;
            }

            float vmax = s1[0];
#pragma unroll
            for (int i = 1; i < 4; i++) vmax = fmaxf(vmax, s1[i]);
#pragma unroll
            for (int i = 0; i < 4; i++) vmax = fmaxf(vmax, s2[i]);
#pragma unroll
            for (int o = 16; o > 0; o >>= 1)
                vmax = fmaxf(vmax, __shfl_xor_sync(0xFFFFFFFFu, vmax, o));

            float e1[4], e2[4], ssum = 0.f;
#pragma unroll
            for (int i = 0; i < 4; i++) { e1[i] = __expf(s1[i] - vmax); ssum += e1[i]; }
#pragma unroll
            for (int i = 0; i < 4; i++) { e2[i] = __expf(s2[i] - vmax); ssum += e2[i]; }
#pragma unroll
            for (int o = 16; o > 0; o >>= 1)
                ssum += __shfl_xor_sync(0xFFFFFFFFu, ssum, o);
            inv[r] = 1.f / ssum;

            *(float4*)&myp[r * KTS + 4 * lane] = make_float4(e1[0], e1[1], e1[2], e1[3]);
            if (lane < 28)
                *(float4*)&myp[r * KTS + 128 + 4 * lane] =
                    make_float4(e2[0], e2[1], e2[2], e2[3]);
        }
        __syncwarp();

        // ---- PV ----
        float o0[4], o1[4], o2[4];
#pragma unroll
        for (int r = 0; r < 4; r++) { o0[r] = 0.f; o1[r] = 0.f; o2[r] = 0.f; }

        const float* vrow0 = vsT + lane * VTS;
        const float* vrow1 = vsT + (lane + 32) * VTS;
        const float* vrow2 = vsT + (lane + 64) * VTS;

#pragma unroll 2
        for (int m4 = 0; m4 < 60; m4++) {
            const int m = m4 * 4;
            float4 p4[4];
#pragma unroll
            for (int r = 0; r < 4; r++)
                p4[r] = *(const float4*)&myp[r * KTS + m];
            const float4 v0 = *(const float4*)(vrow0 + m);
            const float4 v1 = *(const float4*)(vrow1 + m);
            const float4 v2 = *(const float4*)(vrow2 + m);
#pragma unroll
            for (int r = 0; r < 4; r++) {
                o0[r] = fmaf(p4[r].x, v0.x, o0[r]);
                o0[r] = fmaf(p4[r].y, v0.y, o0[r]);
                o0[r] = fmaf(p4[r].z, v0.z, o0[r]);
                o0[r] = fmaf(p4[r].w, v0.w, o0[r]);
                o1[r] = fmaf(p4[r].x, v1.x, o1[r]);
                o1[r] = fmaf(p4[r].y, v1.y, o1[r]);
                o1[r] = fmaf(p4[r].z, v1.z, o1[r]);
                o1[r] = fmaf(p4[r].w, v1.w, o1[r]);
                o2[r] = fmaf(p4[r].x, v2.x, o2[r]);
                o2[r] = fmaf(p4[r].y, v2.y, o2[r]);
                o2[r] = fmaf(p4[r].z, v2.z, o2[r]);
                o2[r] = fmaf(p4[r].w, v2.w, o2[r]);
            }
        }

#pragma unroll
        for (int r = 0; r < 4; r++) {
            size_t ob = (size_t)(b * NTOK + n0 + r) * CDIM + h * HDIM + lane;
            out[ob]      = f2tf_f(o0[r] * inv[r]);
            out[ob + 32] = f2tf_f(o1[r] * inv[r]);
            out[ob + 64] = f2tf_f(o2[r] * inv[r]);
        }
        __syncwarp();
    }
}

// ===========================================================================
// Launch
// ===========================================================================
extern "C" void kernel_launch(void* const* d_in, const int* in_sizes, int n_in,
                              void* d_out, int out_size)
{
    const float* x      = (const float*)d_in[0];   // [64,236,768]
    const float* qkv_w  = (const float*)d_in[1];   // [2304,768]
    const float* proj_w = (const float*)d_in[2];   // [768,768]
    const float* proj_b = (const float*)d_in[3];   // [768]
    float* out = (float*)d_out;                    // [64,236,768]

    float *qkv_buf, *att_buf, *xc, *wqc, *wpc;
    cudaGetSymbolAddress((void**)&qkv_buf, g_qkv);
    cudaGetSymbolAddress((void**)&att_buf, g_att);
    cudaGetSymbolAddress((void**)&xc,  g_xc);
    cudaGetSymbolAddress((void**)&wqc, g_wqc);
    cudaGetSymbolAddress((void**)&wpc, g_wpc);

    cudaFuncSetAttribute(gemm_tf32,
                         cudaFuncAttributeMaxDynamicSharedMemorySize,
                         GEMM_SMEM_BYTES);
    cudaFuncSetAttribute(attn_kernel,
                         cudaFuncAttributeMaxDynamicSharedMemorySize,
                         ATT_SMEM_BYTES);

    // 0) tf32-round inputs once
    {
        int n4;
        n4 = (MROWS * CDIM) / 4;
        cvt_tf32_kernel<<<(n4 + 255) / 256, 256>>>(x, xc, n4);
        n4 = (C3 * CDIM) / 4;
        cvt_tf32_kernel<<<(n4 + 255) / 256, 256>>>(qkv_w, wqc, n4);
        n4 = (CDIM * CDIM) / 4;
        cvt_tf32_kernel<<<(n4 + 255) / 256, 256>>>(proj_w, wpc, n4);
    }

    // 1) QKV projection: [15104,768] @ [2304,768]^T -> [15104,2304]
    {
        dim3 grid(C3 / GBN, MROWS / GBM);   // (9, 118)
        gemm_tf32<<<grid, 256, GEMM_SMEM_BYTES>>>(xc, wqc, nullptr, qkv_buf,
                                                  MROWS, C3, CDIM);
    }

    // 2) Fused attention: 512 CTAs, one per (b,h); output tf32-rounded
    attn_kernel<<<BATCH * HEADS, 256, ATT_SMEM_BYTES>>>(qkv_buf, att_buf);

    // 3) Output projection: [15104,768] @ [768,768]^T + bias -> [15104,768]
    {
        dim3 grid(CDIM / GBN, MROWS / GBM); // (3, 118)
        gemm_tf32<<<grid, 256, GEMM_SMEM_BYTES>>>(att_buf, wpc, proj_b, out,
                                                  MROWS, CDIM, CDIM);
    }
}

// round 6
// speedup vs baseline: 2.3970x; 1.1909x over previous
#include <cuda_runtime.h>
#include <cuda_bf16.h>
#include <math.h>

// Problem constants
#define BATCH   64
#define NTOK    236
#define CDIM    768
#define HEADS   8
#define HDIM    96
#define C3      2304
#define S1C     196
#define S2C     216
#define BIASV   100.0f
#define MROWS   (BATCH * NTOK)   // 15104

// Scratch (device globals; no allocation allowed)
__device__ float g_qkv[(size_t)MROWS * C3];   // [15104, 2304] fp32
__device__ float g_att[(size_t)MROWS * CDIM]; // [15104, 768]  tf32-rounded
__device__ float g_xc [(size_t)MROWS * CDIM]; // x, tf32-rounded
__device__ float g_wqc[(size_t)C3 * CDIM];    // qkv_w, tf32-rounded
__device__ float g_wpc[(size_t)CDIM * CDIM];  // proj_w, tf32-rounded

__device__ __forceinline__ unsigned f2tf(unsigned x) {
    unsigned y;
    asm volatile("cvt.rna.tf32.f32 %0, %1;\n" : "=r"(y) : "r"(x));
    return y;
}
__device__ __forceinline__ float f2tf_f(float x) {
    return __uint_as_float(f2tf(__float_as_uint(x)));
}

// ---------------------------------------------------------------------------
// Elementwise fp32 -> tf32(rna) pre-conversion (vectorized)
// ---------------------------------------------------------------------------
__global__ __launch_bounds__(256) void cvt_tf32_kernel(
    const float* __restrict__ in, float* __restrict__ out, int n4)
{
    int i = blockIdx.x * blockDim.x + threadIdx.x;
    if (i < n4) {
        float4 v = ((const float4*)in)[i];
        v.x = f2tf_f(v.x); v.y = f2tf_f(v.y);
        v.z = f2tf_f(v.z); v.w = f2tf_f(v.w);
        ((float4*)out)[i] = v;
    }
}

// ===========================================================================
// TF32 tensor-core GEMM:  C[m,n] = sum_k A[m,k] * W[n,k]  (+ bias[n])
// A and W must already be tf32-rounded. Block 128x128x32, 8 warps (2x4),
// warp tile 64x32, cp.async 3-stage pipeline, swizzled smem, 2 CTAs/SM.
// ===========================================================================
#define GBM 128
#define GBN 128
#define GBK 32
#define NSTAGE 3
#define A_TILE_B 16384                 // 128 rows * 8 chunks * 16B
#define B_TILE_B 16384
#define STAGE_B  (A_TILE_B + B_TILE_B) // 32768
#define GEMM_SMEM_BYTES (NSTAGE * STAGE_B)   // 98304

__device__ __forceinline__ void cp16(unsigned dst, const void* src) {
    asm volatile("cp.async.cg.shared.global [%0], [%1], 16;\n" :: "r"(dst), "l"(src));
}
__device__ __forceinline__ void cp_commit() {
    asm volatile("cp.async.commit_group;\n" ::);
}
__device__ __forceinline__ void cp_wait1() {
    asm volatile("cp.async.wait_group 1;\n" ::);
}

__device__ __forceinline__ void ldsm4(unsigned* r, unsigned addr) {
    asm volatile("ldmatrix.sync.aligned.m8n8.x4.shared.b16 {%0,%1,%2,%3}, [%4];\n"
        : "=r"(r[0]), "=r"(r[1]), "=r"(r[2]), "=r"(r[3]) : "r"(addr));
}

__device__ __forceinline__ void mma_tf32(float* c, const unsigned* a,
                                         unsigned b0, unsigned b1) {
    asm volatile(
        "mma.sync.aligned.m16n8k8.row.col.f32.tf32.tf32.f32 "
        "{%0,%1,%2,%3}, {%4,%5,%6,%7}, {%8,%9}, {%0,%1,%2,%3};\n"
        : "+f"(c[0]), "+f"(c[1]), "+f"(c[2]), "+f"(c[3])
        : "r"(a[0]), "r"(a[1]), "r"(a[2]), "r"(a[3]), "r"(b0), "r"(b1));
}

__device__ __forceinline__ unsigned swz(int row, int c) {
    return (unsigned)((row * 8 + (c ^ (row & 7))) * 16);
}

__global__ __launch_bounds__(256, 2) void gemm_tf32(
    const float* __restrict__ A, const float* __restrict__ W,
    const float* __restrict__ bias, float* __restrict__ C,
    int M, int Nc, int K)
{
    extern __shared__ char smc[];
    const unsigned smem_u = (unsigned)__cvta_generic_to_shared(smc);

    const int tid = threadIdx.x;
    const int lane = tid & 31, wid = tid >> 5;
    const int wm = wid & 1, wn = wid >> 1;       // 2 x 4 warp grid
    const int m0 = blockIdx.y * GBM, n0 = blockIdx.x * GBN;

    // staging mapping: 2 threads per row, 16 floats (4 chunks) each
    const int ar = tid >> 1;                     // row 0..127
    const int ac = (tid & 1) * 4;                // chunk group 0 / 4
    const float* agp = A + (size_t)(m0 + ar) * K + ac * 4;
    const float* bgp = W + (size_t)(n0 + ar) * K + ac * 4;
    unsigned aoff[4], boff[4];
#pragma unroll
    for (int q = 0; q < 4; q++) {
        aoff[q] = swz(ar, ac + q);
        boff[q] = A_TILE_B + swz(ar, ac + q);
    }

#define ISSUE_STAGE(KT) do {                                                 \
    unsigned sb = smem_u + ((KT) % NSTAGE) * STAGE_B;                        \
    const float* ag = agp + (KT) * GBK;                                      \
    const float* bg = bgp + (KT) * GBK;                                      \
    _Pragma("unroll")                                                        \
    for (int q = 0; q < 4; q++) cp16(sb + aoff[q], ag + q * 4);              \
    _Pragma("unroll")                                                        \
    for (int q = 0; q < 4; q++) cp16(sb + boff[q], bg + q * 4);              \
} while (0)

    // ldmatrix per-lane row components
    const int t8 = (lane >> 3) & 1;
    const int t16 = lane >> 4;
    const int rr = lane & 7;
    const int rowA = wm * 64 + t8 * 8 + rr;       // + mi*16
    const int rowB = wn * 32 + t16 * 8 + rr;      // + njp*16

    float acc[4][4][4];
#pragma unroll
    for (int i = 0; i < 4; i++)
#pragma unroll
        for (int j = 0; j < 4; j++)
#pragma unroll
            for (int q = 0; q < 4; q++) acc[i][j][q] = 0.f;

    ISSUE_STAGE(0); cp_commit();
    ISSUE_STAGE(1); cp_commit();

    const int nk = K / GBK;
    for (int kt = 0; kt < nk; kt++) {
        cp_wait1();
        __syncthreads();
        if (kt + 2 < nk) { ISSUE_STAGE(kt + 2); }
        cp_commit();

        const unsigned sa = smem_u + (kt % NSTAGE) * STAGE_B;
        const unsigned sbb = sa + A_TILE_B;
#pragma unroll
        for (int ks = 0; ks < 4; ks++) {
            const int ca = 2 * ks + t16;          // A chunk
            const int cb = 2 * ks + t8;           // B chunk
            unsigned af[4][4], bf[2][4];
#pragma unroll
            for (int mi = 0; mi < 4; mi++) {
                int row = rowA + mi * 16;
                ldsm4(af[mi], sa + (unsigned)((row * 8 + (ca ^ (row & 7))) * 16));
            }
#pragma unroll
            for (int njp = 0; njp < 2; njp++) {
                int row = rowB + njp * 16;
                ldsm4(bf[njp], sbb + (unsigned)((row * 8 + (cb ^ (row & 7))) * 16));
            }
#pragma unroll
            for (int mi = 0; mi < 4; mi++)
#pragma unroll
                for (int njp = 0; njp < 2; njp++) {
                    mma_tf32(acc[mi][njp * 2],     af[mi], bf[njp][0], bf[njp][1]);
                    mma_tf32(acc[mi][njp * 2 + 1], af[mi], bf[njp][2], bf[njp][3]);
                }
        }
    }

    // Epilogue
#pragma unroll
    for (int mi = 0; mi < 4; mi++) {
        const int r0 = m0 + wm * 64 + mi * 16 + (lane >> 2);
#pragma unroll
        for (int nj = 0; nj < 4; nj++) {
            const int c0 = n0 + wn * 32 + nj * 8 + (lane & 3) * 2;
            float b0 = 0.f, b1 = 0.f;
            if (bias) { b0 = bias[c0]; b1 = bias[c0 + 1]; }
            *(float2*)(C + (size_t)r0 * Nc + c0) =
                make_float2(acc[mi][nj][0] + b0, acc[mi][nj][1] + b1);
            *(float2*)(C + (size_t)(r0 + 8) * Nc + c0) =
                make_float2(acc[mi][nj][2] + b0, acc[mi][nj][3] + b1);
        }
    }
#undef ISSUE_STAGE
}

// ===========================================================================
// Fused attention per (b,h). K,V stored TRANSPOSED in smem: ksT[d][m],
// vsT[d][m]. Scores kept in registers; block edits + softmax via shuffles.
// Output written tf32-rounded (feeds the proj GEMM directly).
// ===========================================================================
#define KTS 240                       // ksT row stride (floats)
#define VTS 244                       // vsT row stride (floats)
#define SM_KT (HDIM * KTS)            // 23040
#define SM_VT (HDIM * VTS)            // 23424
#define SM_Q  (8 * 4 * HDIM)          // 3072
#define SM_P  (8 * 4 * KTS)           // 7680
#define ATT_SMEM_FLOATS (SM_KT + SM_VT + SM_Q + SM_P)
#define ATT_SMEM_BYTES  (ATT_SMEM_FLOATS * 4)   // 228864

__global__ __launch_bounds__(256) void attn_kernel(
    const float* __restrict__ qkv, float* __restrict__ out)
{
    extern __shared__ float smf[];
    float* ksT = smf;                  // [96][240]
    float* vsT = ksT + SM_KT;          // [96][244]
    float* qs  = vsT + SM_VT;          // [8][4][96]
    float* ps  = qs + SM_Q;            // [8][4][240]

    const int bh = blockIdx.x;
    const int b = bh >> 3, h = bh & 7;
    const int tid = threadIdx.x;
    const int w = tid >> 5, lane = tid & 31;
    const float scale = 0.1020620726159658f;   // 96^-0.5

    const size_t base = (size_t)b * NTOK * C3;

    // Stage K,V transposed. idx -> (chunk c of 4 d-values, m)
    for (int idx = tid; idx < 24 * 256; idx += 256) {
        const int c = idx >> 8;
        const int m = idx & 255;
        if (m < 240) {
            float4 kv = make_float4(0.f, 0.f, 0.f, 0.f);
            float4 vv = kv;
            if (m < NTOK) {
                const float* row = qkv + base + (size_t)m * C3 + h * HDIM + c * 4;
                kv = *(const float4*)(row + CDIM);
                vv = *(const float4*)(row + 2 * CDIM);
            }
            const int d = c * 4;
            ksT[(d + 0) * KTS + m] = kv.x;
            ksT[(d + 1) * KTS + m] = kv.y;
            ksT[(d + 2) * KTS + m] = kv.z;
            ksT[(d + 3) * KTS + m] = kv.w;
            vsT[(d + 0) * VTS + m] = vv.x;
            vsT[(d + 1) * VTS + m] = vv.y;
            vsT[(d + 2) * VTS + m] = vv.z;
            vsT[(d + 3) * VTS + m] = vv.w;
        }
    }
    __syncthreads();

    float* myq = qs + w * (4 * HDIM);
    float* myp = ps + w * (4 * KTS);
    const int c2 = (lane < 28) ? (128 + 4 * lane) : 128;

    for (int g = w; g < 59; g += 8) {
        const int n0 = g * 4;

        // stage 4 q rows, scale folded in
        for (int i = lane; i < HDIM; i += 32) {
#pragma unroll
            for (int r = 0; r < 4; r++)
                myq[r * HDIM + i] =
                    qkv[base + (size_t)(n0 + r) * C3 + h * HDIM + i] * scale;
        }
        __syncwarp();

        // ---- QK^T ----
        float acc[4][8];
#pragma unroll
        for (int r = 0; r < 4; r++)
#pragma unroll
            for (int j = 0; j < 8; j++) acc[r][j] = 0.f;

        for (int d4 = 0; d4 < 24; d4++) {
            float4 q4[4];
#pragma unroll
            for (int r = 0; r < 4; r++)
                q4[r] = *(const float4*)&myq[r * HDIM + d4 * 4];
#pragma unroll
            for (int dd = 0; dd < 4; dd++) {
                const int d = d4 * 4 + dd;
                const float4 k1 = *(const float4*)&ksT[d * KTS + 4 * lane];
                const float4 k2 = *(const float4*)&ksT[d * KTS + c2];
                const float qr[4] = {
                    dd == 0 ? q4[0].x : dd == 1 ? q4[0].y : dd == 2 ? q4[0].z : q4[0].w,
                    dd == 0 ? q4[1].x : dd == 1 ? q4[1].y : dd == 2 ? q4[1].z : q4[1].w,
                    dd == 0 ? q4[2].x : dd == 1 ? q4[2].y : dd == 2 ? q4[2].z : q4[2].w,
                    dd == 0 ? q4[3].x : dd == 1 ? q4[3].y : dd == 2 ? q4[3].z : q4[3].w };
#pragma unroll
                for (int r = 0; r < 4; r++) {
                    acc[r][0] = fmaf(qr[r], k1.x, acc[r][0]);
                    acc[r][1] = fmaf(qr[r], k1.y, acc[r][1]);
                    acc[r][2] = fmaf(qr[r], k1.z, acc[r][2]);
                    acc[r][3] = fmaf(qr[r], k1.w, acc[r][3]);
                    acc[r][4] = fmaf(qr[r], k2.x, acc[r][4]);
                    acc[r][5] = fmaf(qr[r], k2.y, acc[r][5]);
                    acc[r][6] = fmaf(qr[r], k2.z, acc[r][6]);
                    acc[r][7] = fmaf(qr[r], k2.w, acc[r][7]);
                }
            }
        }

        // ---- edits + softmax (registers), store p ----
        float inv[4];
#pragma unroll
        for (int r = 0; r < 4; r++) {
            const int n = n0 + r;
            float s1[4], s2[4];
#pragma unroll
            for (int i = 0; i < 4; i++) { s1[i] = acc[r][i]; s2[i] = acc[r][4 + i]; }

            // copy source (cols 196..215 live in lanes 17..21; dst lanes 22..26)
            float src[4];
#pragma unroll
            for (int i = 0; i < 4; i++)
                src[i] = __shfl_sync(0xFFFFFFFFu, s2[i], (lane - 5) & 31);

            if (n < S1C) {
                if (lane >= 22 && lane <= 26) {
#pragma unroll
                    for (int i = 0; i < 4; i++) s2[i] = src[i];
                }
                if (lane >= 17 && lane <= 21) {
#pragma unroll
                    for (int i = 0; i < 4; i++) s2[i] -= BIASV;
                }
            } else if (n < S2C) {
                if (lane >= 22 && lane <= 26) {
#pragma unroll
                    for (int i = 0; i < 4; i++) s2[i] -= BIASV;
                }
            } else {
                if (lane >= 17 && lane <= 21) {
#pragma unroll
                    for (int i = 0; i < 4; i++) s2[i] -= BIASV;
                }
            }
            if (lane >= 27) {
#pragma unroll
                for (int i = 0; i < 4; i++) s2[i] = -1e30f;
            }

            float vmax = s1[0];
#pragma unroll
            for (int i = 1; i < 4; i++) vmax = fmaxf(vmax, s1[i]);
#pragma unroll
            for (int i = 0; i < 4; i++) vmax = fmaxf(vmax, s2[i]);
#pragma unroll
            for (int o = 16; o > 0; o >>= 1)
                vmax = fmaxf(vmax, __shfl_xor_sync(0xFFFFFFFFu, vmax, o));

            float e1[4], e2[4], ssum = 0.f;
#pragma unroll
            for (int i = 0; i < 4; i++) { e1[i] = __expf(s1[i] - vmax); ssum += e1[i]; }
#pragma unroll
            for (int i = 0; i < 4; i++) { e2[i] = __expf(s2[i] - vmax); ssum += e2[i]; }
#pragma unroll
            for (int o = 16; o > 0; o >>= 1)
                ssum += __shfl_xor_sync(0xFFFFFFFFu, ssum, o);
            inv[r] = 1.f / ssum;

            *(float4*)&myp[r * KTS + 4 * lane] = make_float4(e1[0], e1[1], e1[2], e1[3]);
            if (lane < 28)
                *(float4*)&myp[r * KTS + 128 + 4 * lane] =
                    make_float4(e2[0], e2[1], e2[2], e2[3]);
        }
        __syncwarp();

        // ---- PV ----
        float o0[4], o1[4], o2[4];
#pragma unroll
        for (int r = 0; r < 4; r++) { o0[r] = 0.f; o1[r] = 0.f; o2[r] = 0.f; }

        const float* vrow0 = vsT + lane * VTS;
        const float* vrow1 = vsT + (lane + 32) * VTS;
        const float* vrow2 = vsT + (lane + 64) * VTS;

#pragma unroll 2
        for (int m4 = 0; m4 < 60; m4++) {
            const int m = m4 * 4;
            float4 p4[4];
#pragma unroll
            for (int r = 0; r < 4; r++)
                p4[r] = *(const float4*)&myp[r * KTS + m];
            const float4 v0 = *(const float4*)(vrow0 + m);
            const float4 v1 = *(const float4*)(vrow1 + m);
            const float4 v2 = *(const float4*)(vrow2 + m);
#pragma unroll
            for (int r = 0; r < 4; r++) {
                o0[r] = fmaf(p4[r].x, v0.x, o0[r]);
                o0[r] = fmaf(p4[r].y, v0.y, o0[r]);
                o0[r] = fmaf(p4[r].z, v0.z, o0[r]);
                o0[r] = fmaf(p4[r].w, v0.w, o0[r]);
                o1[r] = fmaf(p4[r].x, v1.x, o1[r]);
                o1[r] = fmaf(p4[r].y, v1.y, o1[r]);
                o1[r] = fmaf(p4[r].z, v1.z, o1[r]);
                o1[r] = fmaf(p4[r].w, v1.w, o1[r]);
                o2[r] = fmaf(p4[r].x, v2.x, o2[r]);
                o2[r] = fmaf(p4[r].y, v2.y, o2[r]);
                o2[r] = fmaf(p4[r].z, v2.z, o2[r]);
                o2[r] = fmaf(p4[r].w, v2.w, o2[r]);
            }
        }

#pragma unroll
        for (int r = 0; r < 4; r++) {
            size_t ob = (size_t)(b * NTOK + n0 + r) * CDIM + h * HDIM + lane;
            out[ob]      = f2tf_f(o0[r] * inv[r]);
            out[ob + 32] = f2tf_f(o1[r] * inv[r]);
            out[ob + 64] = f2tf_f(o2[r] * inv[r]);
        }
        __syncwarp();
    }
}

// ===========================================================================
// Launch
// ===========================================================================
extern "C" void kernel_launch(void* const* d_in, const int* in_sizes, int n_in,
                              void* d_out, int out_size)
{
    const float* x      = (const float*)d_in[0];   // [64,236,768]
    const float* qkv_w  = (const float*)d_in[1];   // [2304,768]
    const float* proj_w = (const float*)d_in[2];   // [768,768]
    const float* proj_b = (const float*)d_in[3];   // [768]
    float* out = (float*)d_out;                    // [64,236,768]

    float *qkv_buf, *att_buf, *xc, *wqc, *wpc;
    cudaGetSymbolAddress((void**)&qkv_buf, g_qkv);
    cudaGetSymbolAddress((void**)&att_buf, g_att);
    cudaGetSymbolAddress((void**)&xc,  g_xc);
    cudaGetSymbolAddress((void**)&wqc, g_wqc);
    cudaGetSymbolAddress((void**)&wpc, g_wpc);

    cudaFuncSetAttribute(gemm_tf32,
                         cudaFuncAttributeMaxDynamicSharedMemorySize,
                         GEMM_SMEM_BYTES);
    cudaFuncSetAttribute(attn_kernel,
                         cudaFuncAttributeMaxDynamicSharedMemorySize,
                         ATT_SMEM_BYTES);

    // 0) tf32-round inputs once
    {
        int n4;
        n4 = (MROWS * CDIM) / 4;
        cvt_tf32_kernel<<<(n4 + 255) / 256, 256>>>(x, xc, n4);
        n4 = (C3 * CDIM) / 4;
        cvt_tf32_kernel<<<(n4 + 255) / 256, 256>>>(qkv_w, wqc, n4);
        n4 = (CDIM * CDIM) / 4;
        cvt_tf32_kernel<<<(n4 + 255) / 256, 256>>>(proj_w, wpc, n4);
    }

    // 1) QKV projection: [15104,768] @ [2304,768]^T -> [15104,2304]
    {
        dim3 grid(C3 / GBN, MROWS / GBM);   // (18, 118)
        gemm_tf32<<<grid, 256, GEMM_SMEM_BYTES>>>(xc, wqc, nullptr, qkv_buf,
                                                  MROWS, C3, CDIM);
    }

    // 2) Fused attention: 512 CTAs, one per (b,h); output tf32-rounded
    attn_kernel<<<BATCH * HEADS, 256, ATT_SMEM_BYTES>>>(qkv_buf, att_buf);

    // 3) Output projection: [15104,768] @ [768,768]^T + bias -> [15104,768]
    {
        dim3 grid(CDIM / GBN, MROWS / GBM); // (6, 118)
        gemm_tf32<<<grid, 256, GEMM_SMEM_BYTES>>>(att_buf, wpc, proj_b, out,
                                                  MROWS, CDIM, CDIM);
    }
}

// round 7
// speedup vs baseline: 3.7039x; 1.5452x over previous
#include <cuda_runtime.h>
#include <cuda_bf16.h>
#include <math.h>

// Problem constants
#define BATCH   64
#define NTOK    236
#define CDIM    768
#define HEADS   8
#define HDIM    96
#define C3      2304
#define S1C     196
#define S2C     216
#define BIASV   100.0f
#define MROWS   (BATCH * NTOK)   // 15104

// Scratch (device globals; no allocation allowed)
__device__ float g_qkv[(size_t)MROWS * C3];   // [15104, 2304] fp32
__device__ float g_att[(size_t)MROWS * CDIM]; // [15104, 768]  tf32-rounded
__device__ float g_xc [(size_t)MROWS * CDIM]; // x, tf32-rounded
__device__ float g_wqc[(size_t)C3 * CDIM];    // qkv_w, tf32-rounded
__device__ float g_wpc[(size_t)CDIM * CDIM];  // proj_w, tf32-rounded

__device__ __forceinline__ unsigned f2tf(unsigned x) {
    unsigned y;
    asm volatile("cvt.rna.tf32.f32 %0, %1;\n" : "=r"(y) : "r"(x));
    return y;
}
__device__ __forceinline__ float f2tf_f(float x) {
    return __uint_as_float(f2tf(__float_as_uint(x)));
}

// ---------------------------------------------------------------------------
// Elementwise fp32 -> tf32(rna) pre-conversion (vectorized)
// ---------------------------------------------------------------------------
__global__ __launch_bounds__(256) void cvt_tf32_kernel(
    const float* __restrict__ in, float* __restrict__ out, int n4)
{
    int i = blockIdx.x * blockDim.x + threadIdx.x;
    if (i < n4) {
        float4 v = ((const float4*)in)[i];
        v.x = f2tf_f(v.x); v.y = f2tf_f(v.y);
        v.z = f2tf_f(v.z); v.w = f2tf_f(v.w);
        ((float4*)out)[i] = v;
    }
}

// ---------------------------------------------------------------------------
// Shared MMA helpers
// ---------------------------------------------------------------------------
__device__ __forceinline__ void ldsm4(unsigned* r, unsigned addr) {
    asm volatile("ldmatrix.sync.aligned.m8n8.x4.shared.b16 {%0,%1,%2,%3}, [%4];\n"
        : "=r"(r[0]), "=r"(r[1]), "=r"(r[2]), "=r"(r[3]) : "r"(addr));
}
__device__ __forceinline__ void mma_tf32(float* c, const unsigned* a,
                                         unsigned b0, unsigned b1) {
    asm volatile(
        "mma.sync.aligned.m16n8k8.row.col.f32.tf32.tf32.f32 "
        "{%0,%1,%2,%3}, {%4,%5,%6,%7}, {%8,%9}, {%0,%1,%2,%3};\n"
        : "+f"(c[0]), "+f"(c[1]), "+f"(c[2]), "+f"(c[3])
        : "r"(a[0]), "r"(a[1]), "r"(a[2]), "r"(a[3]), "r"(b0), "r"(b1));
}

// ===========================================================================
// TF32 tensor-core GEMM:  C[m,n] = sum_k A[m,k] * W[n,k]  (+ bias[n])
// Block 128x128x32, 8 warps (2x4), warp tile 64x32, cp.async 3-stage,
// swizzled smem, 2 CTAs/SM.  (unchanged from R6)
// ===========================================================================
#define GBM 128
#define GBN 128
#define GBK 32
#define NSTAGE 3
#define A_TILE_B 16384
#define B_TILE_B 16384
#define STAGE_B  (A_TILE_B + B_TILE_B)
#define GEMM_SMEM_BYTES (NSTAGE * STAGE_B)   // 98304

__device__ __forceinline__ void cp16(unsigned dst, const void* src) {
    asm volatile("cp.async.cg.shared.global [%0], [%1], 16;\n" :: "r"(dst), "l"(src));
}
__device__ __forceinline__ void cp_commit() {
    asm volatile("cp.async.commit_group;\n" ::);
}
__device__ __forceinline__ void cp_wait1() {
    asm volatile("cp.async.wait_group 1;\n" ::);
}
__device__ __forceinline__ unsigned swz(int row, int c) {
    return (unsigned)((row * 8 + (c ^ (row & 7))) * 16);
}

__global__ __launch_bounds__(256, 2) void gemm_tf32(
    const float* __restrict__ A, const float* __restrict__ W,
    const float* __restrict__ bias, float* __restrict__ C,
    int M, int Nc, int K)
{
    extern __shared__ char smc[];
    const unsigned smem_u = (unsigned)__cvta_generic_to_shared(smc);

    const int tid = threadIdx.x;
    const int lane = tid & 31, wid = tid >> 5;
    const int wm = wid & 1, wn = wid >> 1;
    const int m0 = blockIdx.y * GBM, n0 = blockIdx.x * GBN;

    const int ar = tid >> 1;
    const int ac = (tid & 1) * 4;
    const float* agp = A + (size_t)(m0 + ar) * K + ac * 4;
    const float* bgp = W + (size_t)(n0 + ar) * K + ac * 4;
    unsigned aoff[4], boff[4];
#pragma unroll
    for (int q = 0; q < 4; q++) {
        aoff[q] = swz(ar, ac + q);
        boff[q] = A_TILE_B + swz(ar, ac + q);
    }

#define ISSUE_STAGE(KT) do {                                                 \
    unsigned sb = smem_u + ((KT) % NSTAGE) * STAGE_B;                        \
    const float* ag = agp + (KT) * GBK;                                      \
    const float* bg = bgp + (KT) * GBK;                                      \
    _Pragma("unroll")                                                        \
    for (int q = 0; q < 4; q++) cp16(sb + aoff[q], ag + q * 4);              \
    _Pragma("unroll")                                                        \
    for (int q = 0; q < 4; q++) cp16(sb + boff[q], bg + q * 4);              \
} while (0)

    const int t8 = (lane >> 3) & 1;
    const int t16 = lane >> 4;
    const int rr = lane & 7;
    const int rowA = wm * 64 + t8 * 8 + rr;
    const int rowB = wn * 32 + t16 * 8 + rr;

    float acc[4][4][4];
#pragma unroll
    for (int i = 0; i < 4; i++)
#pragma unroll
        for (int j = 0; j < 4; j++)
#pragma unroll
            for (int q = 0; q < 4; q++) acc[i][j][q] = 0.f;

    ISSUE_STAGE(0); cp_commit();
    ISSUE_STAGE(1); cp_commit();

    const int nk = K / GBK;
    for (int kt = 0; kt < nk; kt++) {
        cp_wait1();
        __syncthreads();
        if (kt + 2 < nk) { ISSUE_STAGE(kt + 2); }
        cp_commit();

        const unsigned sa = smem_u + (kt % NSTAGE) * STAGE_B;
        const unsigned sbb = sa + A_TILE_B;
#pragma unroll
        for (int ks = 0; ks < 4; ks++) {
            const int ca = 2 * ks + t16;
            const int cb = 2 * ks + t8;
            unsigned af[4][4], bf[2][4];
#pragma unroll
            for (int mi = 0; mi < 4; mi++) {
                int row = rowA + mi * 16;
                ldsm4(af[mi], sa + (unsigned)((row * 8 + (ca ^ (row & 7))) * 16));
            }
#pragma unroll
            for (int njp = 0; njp < 2; njp++) {
                int row = rowB + njp * 16;
                ldsm4(bf[njp], sbb + (unsigned)((row * 8 + (cb ^ (row & 7))) * 16));
            }
#pragma unroll
            for (int mi = 0; mi < 4; mi++)
#pragma unroll
                for (int njp = 0; njp < 2; njp++) {
                    mma_tf32(acc[mi][njp * 2],     af[mi], bf[njp][0], bf[njp][1]);
                    mma_tf32(acc[mi][njp * 2 + 1], af[mi], bf[njp][2], bf[njp][3]);
                }
        }
    }

#pragma unroll
    for (int mi = 0; mi < 4; mi++) {
        const int r0 = m0 + wm * 64 + mi * 16 + (lane >> 2);
#pragma unroll
        for (int nj = 0; nj < 4; nj++) {
            const int c0 = n0 + wn * 32 + nj * 8 + (lane & 3) * 2;
            float b0 = 0.f, b1 = 0.f;
            if (bias) { b0 = bias[c0]; b1 = bias[c0 + 1]; }
            *(float2*)(C + (size_t)r0 * Nc + c0) =
                make_float2(acc[mi][nj][0] + b0, acc[mi][nj][1] + b1);
            *(float2*)(C + (size_t)(r0 + 8) * Nc + c0) =
                make_float2(acc[mi][nj][2] + b0, acc[mi][nj][3] + b1);
        }
    }
#undef ISSUE_STAGE
}

// ===========================================================================
// Tensor-core attention. One CTA per (b,h), 8 warps. Each warp processes
// 16 query rows per pass (2 passes). S = QK^T via tf32 mma (scores stay in
// registers), block edits + softmax via shuffles in fragment domain,
// O = P@V via tf32 mma. K in smem [240][96], V^T in smem [96][256], both
// tf32-rounded, group-XOR-swizzled for conflict-free ldmatrix.
// ===========================================================================
#define AK_ROWS   240
#define AK_FLOATS (AK_ROWS * 96)      // 23040
#define AV_FLOATS (96 * 256)          // 24576
#define ATT_SMEM_BYTES ((AK_FLOATS + AV_FLOATS) * 4)   // 190464

__global__ __launch_bounds__(256, 1) void attn_tc_kernel(
    const float* __restrict__ qkv, float* __restrict__ out)
{
    extern __shared__ float smf[];
    float* ks  = smf;                  // [240][96]  (token-major, k-contig)
    float* vsT = smf + AK_FLOATS;      // [96][256]  (d-major, token-contig)
    const unsigned ks_u = (unsigned)__cvta_generic_to_shared(ks);
    const unsigned vs_u = (unsigned)__cvta_generic_to_shared(vsT);

    const int bh = blockIdx.x;
    const int b = bh >> 3, h = bh & 7;
    const int tid = threadIdx.x;
    const int w = tid >> 5, lane = tid & 31;
    const float scale = 0.1020620726159658f;   // 96^-0.5
    const size_t base = (size_t)b * NTOK * C3;

    // ---- stage K: rows 236..239 zeroed; tf32-rounded; XOR swizzle in low
    //      3 chunk bits (chunk = 16B) ----
    for (int idx = tid; idx < AK_ROWS * 24; idx += 256) {
        const int m = idx / 24, c = idx - m * 24;
        float4 kv = make_float4(0.f, 0.f, 0.f, 0.f);
        if (m < NTOK)
            kv = *(const float4*)(qkv + base + (size_t)m * C3 + CDIM + h * HDIM + c * 4);
        kv.x = f2tf_f(kv.x); kv.y = f2tf_f(kv.y);
        kv.z = f2tf_f(kv.z); kv.w = f2tf_f(kv.w);
        const int cs = (c & 24) | ((c & 7) ^ (m & 7));
        *(float4*)&ks[m * 96 + cs * 4] = kv;
    }
    // ---- stage V^T: tokens 236..239 zeroed ----
    for (int idx = tid; idx < 24 * AK_ROWS; idx += 256) {
        const int c = idx / AK_ROWS;           // d-chunk 0..23
        const int m = idx - c * AK_ROWS;       // token 0..239
        float4 vv = make_float4(0.f, 0.f, 0.f, 0.f);
        if (m < NTOK)
            vv = *(const float4*)(qkv + base + (size_t)m * C3 + 2 * CDIM + h * HDIM + c * 4);
        const int ch = m >> 2, mi = m & 3;
        float e[4] = {vv.x, vv.y, vv.z, vv.w};
#pragma unroll
        for (int j = 0; j < 4; j++) {
            const int d = c * 4 + j;
            const int chp = (ch & ~7) | ((ch & 7) ^ (d & 7));
            vsT[d * 256 + chp * 4 + mi] = f2tf_f(e[j]);
        }
    }
    __syncthreads();

    const int t8 = (lane >> 3) & 1, t16 = lane >> 4, rr = lane & 7;
    const int lp = lane & 3;      // col-pair slot within quad
    const int lq = lane >> 2;     // row within frag (0..7)
    const bool plo = lp < 2;
    const bool kodd = (lp & 1) != 0;
    const int srcl  = (lane & ~3) | (lp >> 1);
    const int srcl2 = (lane & ~3) | ((lp >> 1) + 2);

#pragma unroll 1
    for (int pass = 0; pass < 2; pass++) {
        const int rowbase = pass * 128 + w * 16;
        if (rowbase >= NTOK) continue;

        // ---- Q A-frags via direct LDG (tf32-rounded, scale folded) ----
        unsigned qa[12][4];
        {
            const int r0 = rowbase + lq;
            const int r1 = r0 + 8;
            const int rc0 = r0 < NTOK ? r0 : NTOK - 1;
            const int rc1 = r1 < NTOK ? r1 : NTOK - 1;
            const float* q0 = qkv + base + (size_t)rc0 * C3 + h * HDIM;
            const float* q1 = qkv + base + (size_t)rc1 * C3 + h * HDIM;
#pragma unroll
            for (int kf = 0; kf < 12; kf++) {
                const int k0 = kf * 8 + lp;
                qa[kf][0] = f2tf(__float_as_uint(q0[k0] * scale));
                qa[kf][1] = f2tf(__float_as_uint(q1[k0] * scale));
                qa[kf][2] = f2tf(__float_as_uint(q0[k0 + 4] * scale));
                qa[kf][3] = f2tf(__float_as_uint(q1[k0 + 4] * scale));
            }
        }

        // ---- S = Q K^T : 30 n-frags x 4 regs ----
        float sc[30][4];
#pragma unroll
        for (int nf = 0; nf < 30; nf++)
#pragma unroll
            for (int q = 0; q < 4; q++) sc[nf][q] = 0.f;

#pragma unroll
        for (int g = 0; g < 15; g++) {
            const int row = g * 16 + t16 * 8 + rr;
#pragma unroll
            for (int kf = 0; kf < 12; kf++) {
                const int c = 2 * kf + t8;
                const int cs = (c & 24) | ((c & 7) ^ (row & 7));
                unsigned bf[4];
                ldsm4(bf, ks_u + (unsigned)((row * 96 + cs * 4) * 4));
                mma_tf32(sc[2 * g],     qa[kf], bf[0], bf[1]);
                mma_tf32(sc[2 * g + 1], qa[kf], bf[2], bf[3]);
            }
        }

        // ---- block edits (copy pre-bias, then biases), fragment domain ----
        float t24[4], t25[4], t26[4];
#pragma unroll
        for (int q = 0; q < 4; q++) {
            t24[q] = __shfl_xor_sync(0xFFFFFFFFu, sc[24][q], 2);
            t25[q] = __shfl_xor_sync(0xFFFFFFFFu, sc[25][q], 2);
            t26[q] = __shfl_xor_sync(0xFFFFFFFFu, sc[26][q], 2);
        }
        const int r1 = rowbase + lq;
        const int r2 = r1 + 8;
#pragma unroll
        for (int half = 0; half < 2; half++) {
            const int row = half ? r2 : r1;
            const int o = half * 2;
            if (row < S1C) {
                sc[27][o]     = plo ? t24[o]     : t25[o];
                sc[27][o + 1] = plo ? t24[o + 1] : t25[o + 1];
                sc[28][o]     = plo ? t25[o]     : t26[o];
                sc[28][o + 1] = plo ? t25[o + 1] : t26[o + 1];
                if (plo) { sc[29][o] = t26[o]; sc[29][o + 1] = t26[o + 1]; }
                if (!plo) { sc[24][o] -= BIASV; sc[24][o + 1] -= BIASV; }
                sc[25][o] -= BIASV; sc[25][o + 1] -= BIASV;
                sc[26][o] -= BIASV; sc[26][o + 1] -= BIASV;
            } else if (row < S2C) {
                sc[27][o] -= BIASV; sc[27][o + 1] -= BIASV;
                sc[28][o] -= BIASV; sc[28][o + 1] -= BIASV;
                if (plo) { sc[29][o] -= BIASV; sc[29][o + 1] -= BIASV; }
            } else {
                if (!plo) { sc[24][o] -= BIASV; sc[24][o + 1] -= BIASV; }
                sc[25][o] -= BIASV; sc[25][o + 1] -= BIASV;
                sc[26][o] -= BIASV; sc[26][o + 1] -= BIASV;
            }
        }
        // mask pad columns 236..239
        if (!plo) {
#pragma unroll
            for (int q = 0; q < 4; q++) sc[29][q] = -1e30f;
        }

        // ---- softmax (rows r1: regs 0,1 ; rows r2: regs 2,3) ----
        float mx1 = -1e30f, mx2 = -1e30f;
#pragma unroll
        for (int nf = 0; nf < 30; nf++) {
            mx1 = fmaxf(mx1, fmaxf(sc[nf][0], sc[nf][1]));
            mx2 = fmaxf(mx2, fmaxf(sc[nf][2], sc[nf][3]));
        }
        mx1 = fmaxf(mx1, __shfl_xor_sync(0xFFFFFFFFu, mx1, 1));
        mx1 = fmaxf(mx1, __shfl_xor_sync(0xFFFFFFFFu, mx1, 2));
        mx2 = fmaxf(mx2, __shfl_xor_sync(0xFFFFFFFFu, mx2, 1));
        mx2 = fmaxf(mx2, __shfl_xor_sync(0xFFFFFFFFu, mx2, 2));

        float sum1 = 0.f, sum2 = 0.f;
#pragma unroll
        for (int nf = 0; nf < 30; nf++) {
            sc[nf][0] = __expf(sc[nf][0] - mx1);
            sc[nf][1] = __expf(sc[nf][1] - mx1);
            sc[nf][2] = __expf(sc[nf][2] - mx2);
            sc[nf][3] = __expf(sc[nf][3] - mx2);
            sum1 += sc[nf][0] + sc[nf][1];
            sum2 += sc[nf][2] + sc[nf][3];
        }
        sum1 += __shfl_xor_sync(0xFFFFFFFFu, sum1, 1);
        sum1 += __shfl_xor_sync(0xFFFFFFFFu, sum1, 2);
        sum2 += __shfl_xor_sync(0xFFFFFFFFu, sum2, 1);
        sum2 += __shfl_xor_sync(0xFFFFFFFFu, sum2, 2);
        const float inv1 = 1.f / sum1;
        const float inv2 = 1.f / sum2;

        // ---- O = P @ V ----
        float oc[12][4];
#pragma unroll
        for (int nf = 0; nf < 12; nf++)
#pragma unroll
            for (int q = 0; q < 4; q++) oc[nf][q] = 0.f;

#pragma unroll
        for (int kf = 0; kf < 30; kf++) {
            // convert S c-frag -> P a-frag (shuffle permutation)
            const float v0 = __shfl_sync(0xFFFFFFFFu, sc[kf][0], srcl);
            const float v1 = __shfl_sync(0xFFFFFFFFu, sc[kf][1], srcl);
            const float v2 = __shfl_sync(0xFFFFFFFFu, sc[kf][2], srcl);
            const float v3 = __shfl_sync(0xFFFFFFFFu, sc[kf][3], srcl);
            const float u0 = __shfl_sync(0xFFFFFFFFu, sc[kf][0], srcl2);
            const float u1 = __shfl_sync(0xFFFFFFFFu, sc[kf][1], srcl2);
            const float u2 = __shfl_sync(0xFFFFFFFFu, sc[kf][2], srcl2);
            const float u3 = __shfl_sync(0xFFFFFFFFu, sc[kf][3], srcl2);
            unsigned pa[4];
            pa[0] = f2tf(__float_as_uint(kodd ? v1 : v0));
            pa[1] = f2tf(__float_as_uint(kodd ? v3 : v2));
            pa[2] = f2tf(__float_as_uint(kodd ? u1 : u0));
            pa[3] = f2tf(__float_as_uint(kodd ? u3 : u2));

            const int c = 2 * kf + t8;
#pragma unroll
            for (int dg = 0; dg < 6; dg++) {
                const int d = dg * 16 + t16 * 8 + rr;
                const int cp = (c & ~7) | ((c & 7) ^ (d & 7));
                unsigned bf[4];
                ldsm4(bf, vs_u + (unsigned)((d * 256 + cp * 4) * 4));
                mma_tf32(oc[2 * dg],     pa, bf[0], bf[1]);
                mma_tf32(oc[2 * dg + 1], pa, bf[2], bf[3]);
            }
        }

        // ---- store O (normalized, tf32-rounded for the proj GEMM) ----
#pragma unroll
        for (int nf = 0; nf < 12; nf++) {
            const int col = h * HDIM + nf * 8 + 2 * lp;
            if (r1 < NTOK) {
                float2 v = make_float2(f2tf_f(oc[nf][0] * inv1),
                                       f2tf_f(oc[nf][1] * inv1));
                *(float2*)(out + (size_t)(b * NTOK + r1) * CDIM + col) = v;
            }
            if (r2 < NTOK) {
                float2 v = make_float2(f2tf_f(oc[nf][2] * inv2),
                                       f2tf_f(oc[nf][3] * inv2));
                *(float2*)(out + (size_t)(b * NTOK + r2) * CDIM + col) = v;
            }
        }
    }
}

// ===========================================================================
// Launch
// ===========================================================================
extern "C" void kernel_launch(void* const* d_in, const int* in_sizes, int n_in,
                              void* d_out, int out_size)
{
    const float* x      = (const float*)d_in[0];   // [64,236,768]
    const float* qkv_w  = (const float*)d_in[1];   // [2304,768]
    const float* proj_w = (const float*)d_in[2];   // [768,768]
    const float* proj_b = (const float*)d_in[3];   // [768]
    float* out = (float*)d_out;                    // [64,236,768]

    float *qkv_buf, *att_buf, *xc, *wqc, *wpc;
    cudaGetSymbolAddress((void**)&qkv_buf, g_qkv);
    cudaGetSymbolAddress((void**)&att_buf, g_att);
    cudaGetSymbolAddress((void**)&xc,  g_xc);
    cudaGetSymbolAddress((void**)&wqc, g_wqc);
    cudaGetSymbolAddress((void**)&wpc, g_wpc);

    cudaFuncSetAttribute(gemm_tf32,
                         cudaFuncAttributeMaxDynamicSharedMemorySize,
                         GEMM_SMEM_BYTES);
    cudaFuncSetAttribute(attn_tc_kernel,
                         cudaFuncAttributeMaxDynamicSharedMemorySize,
                         ATT_SMEM_BYTES);

    // 0) tf32-round GEMM inputs once
    {
        int n4;
        n4 = (MROWS * CDIM) / 4;
        cvt_tf32_kernel<<<(n4 + 255) / 256, 256>>>(x, xc, n4);
        n4 = (C3 * CDIM) / 4;
        cvt_tf32_kernel<<<(n4 + 255) / 256, 256>>>(qkv_w, wqc, n4);
        n4 = (CDIM * CDIM) / 4;
        cvt_tf32_kernel<<<(n4 + 255) / 256, 256>>>(proj_w, wpc, n4);
    }

    // 1) QKV projection: [15104,768] @ [2304,768]^T -> [15104,2304]
    {
        dim3 grid(C3 / GBN, MROWS / GBM);   // (18, 118)
        gemm_tf32<<<grid, 256, GEMM_SMEM_BYTES>>>(xc, wqc, nullptr, qkv_buf,
                                                  MROWS, C3, CDIM);
    }

    // 2) Tensor-core attention: 512 CTAs, one per (b,h)
    attn_tc_kernel<<<BATCH * HEADS, 256, ATT_SMEM_BYTES>>>(qkv_buf, att_buf);

    // 3) Output projection: [15104,768] @ [768,768]^T + bias -> [15104,768]
    {
        dim3 grid(CDIM / GBN, MROWS / GBM); // (6, 118)
        gemm_tf32<<<grid, 256, GEMM_SMEM_BYTES>>>(att_buf, wpc, proj_b, out,
                                                  MROWS, CDIM, CDIM);
    }
}